// round 1
// baseline (speedup 1.0000x reference)
#include <cuda_runtime.h>
#include <cuda_bf16.h>
#include <math.h>

// ---------------------------------------------------------------------------
// Problem constants
// ---------------------------------------------------------------------------
constexpr int Bc  = 2;
constexpr int Sc  = 2048;
constexpr int Dc  = 1024;
constexpr int Lc  = 512;
constexpr int Hc  = 8;
constexpr int HDc = 128;
constexpr int Ec  = 8;
constexpr int Fc  = 4096;
constexpr int NT  = Bc * Sc;          // 4096 tokens

// ---------------------------------------------------------------------------
// Scratch: one big __device__ buffer, carved into regions (floats)
// ---------------------------------------------------------------------------
constexpr size_t OFF_XN    = 0;                              // 4096*1024
constexpr size_t OFF_Q     = OFF_XN    + (size_t)NT * Dc;
constexpr size_t OFF_K     = OFF_Q     + (size_t)NT * Dc;
constexpr size_t OFF_V     = OFF_K     + (size_t)NT * Dc;
constexpr size_t OFF_LAT   = OFF_V     + (size_t)NT * Dc;    // 4096*512
constexpr size_t OFF_AO    = OFF_LAT   + (size_t)NT * Lc;
constexpr size_t OFF_H     = OFF_AO    + (size_t)NT * Dc;
constexpr size_t OFF_HN    = OFF_H     + (size_t)NT * Dc;
constexpr size_t OFF_ACT   = OFF_HN    + (size_t)NT * Dc;    // 2*4096*4096
constexpr size_t OFF_MOE   = OFF_ACT   + (size_t)2 * NT * Fc; // 2*4096*1024
constexpr size_t OFF_WSLOT = OFF_MOE   + (size_t)2 * NT * Dc; // 2*4096
constexpr size_t OFF_ELIST = OFF_WSLOT + (size_t)2 * NT;      // 8*4096 ints
constexpr size_t OFF_ECNT  = OFF_ELIST + (size_t)Ec * NT;     // 8 ints
constexpr size_t BUF_TOTAL = OFF_ECNT + 64;

__device__ float g_buf[BUF_TOTAL];

// ---------------------------------------------------------------------------
// Reset expert counters
// ---------------------------------------------------------------------------
__global__ void reset_kernel(int* ecount) {
    if (threadIdx.x < Ec) ecount[threadIdx.x] = 0;
}

// ---------------------------------------------------------------------------
// LayerNorm: one block per token, 256 threads
// ---------------------------------------------------------------------------
__global__ __launch_bounds__(256) void ln_kernel(
    const float* __restrict__ x, const float* __restrict__ g,
    const float* __restrict__ b, float* __restrict__ y)
{
    int t = blockIdx.x;
    int tid = threadIdx.x;
    const float* xr = x + (size_t)t * Dc;
    float s = 0.f, s2 = 0.f;
    #pragma unroll
    for (int i = tid; i < Dc; i += 256) { float v = xr[i]; s += v; s2 += v * v; }
    __shared__ float sh[2][256];
    sh[0][tid] = s; sh[1][tid] = s2;
    __syncthreads();
    for (int st = 128; st > 0; st >>= 1) {
        if (tid < st) { sh[0][tid] += sh[0][tid + st]; sh[1][tid] += sh[1][tid + st]; }
        __syncthreads();
    }
    float mu   = sh[0][0] * (1.f / Dc);
    float var  = sh[1][0] * (1.f / Dc) - mu * mu;
    float rstd = rsqrtf(var + 1e-5f);
    float* yr = y + (size_t)t * Dc;
    #pragma unroll
    for (int i = tid; i < Dc; i += 256)
        yr[i] = (xr[i] - mu) * rstd * g[i] + b[i];
}

// ---------------------------------------------------------------------------
// SGEMM 128x128x8, 256 threads, 8x8 micro-tile, optional residual add
// Requires M%128==0, N%128==0, K%8==0 (true for all call sites)
// ---------------------------------------------------------------------------
__global__ __launch_bounds__(256) void sgemm128(
    const float* __restrict__ A, const float* __restrict__ Bm,
    const float* __restrict__ resid, float* __restrict__ C,
    int M, int Kd, int Nn)
{
    __shared__ float As[8][136];
    __shared__ float Bs[8][128];
    int tid = threadIdx.x;
    int tx = tid & 15, ty = tid >> 4;
    int m0 = blockIdx.y * 128, n0 = blockIdx.x * 128;

    int ar = tid >> 1, ac = (tid & 1) * 4;   // A: 128 rows x 8 cols
    int br = tid >> 5, bc = (tid & 31) * 4;  // B: 8 rows x 128 cols

    const float* Aptr = A + (size_t)(m0 + ar) * Kd + ac;
    const float* Bptr = Bm + (size_t)br * Nn + n0 + bc;

    float acc[8][8];
    #pragma unroll
    for (int i = 0; i < 8; i++)
        #pragma unroll
        for (int j = 0; j < 8; j++) acc[i][j] = 0.f;

    for (int k0 = 0; k0 < Kd; k0 += 8) {
        float4 av = *(const float4*)(Aptr + k0);
        float4 bv = *(const float4*)(Bptr + (size_t)k0 * Nn);
        As[ac + 0][ar] = av.x; As[ac + 1][ar] = av.y;
        As[ac + 2][ar] = av.z; As[ac + 3][ar] = av.w;
        *(float4*)&Bs[br][bc] = bv;
        __syncthreads();
        #pragma unroll
        for (int kk = 0; kk < 8; kk++) {
            float a[8], b[8];
            *(float4*)&a[0] = *(const float4*)&As[kk][ty * 8];
            *(float4*)&a[4] = *(const float4*)&As[kk][ty * 8 + 4];
            *(float4*)&b[0] = *(const float4*)&Bs[kk][tx * 8];
            *(float4*)&b[4] = *(const float4*)&Bs[kk][tx * 8 + 4];
            #pragma unroll
            for (int i = 0; i < 8; i++)
                #pragma unroll
                for (int j = 0; j < 8; j++)
                    acc[i][j] = fmaf(a[i], b[j], acc[i][j]);
        }
        __syncthreads();
    }

    #pragma unroll
    for (int i = 0; i < 8; i++) {
        size_t row = (size_t)(m0 + ty * 8 + i);
        float* cp = C + row * Nn + n0 + tx * 8;
        if (resid) {
            const float* rp = resid + row * Nn + n0 + tx * 8;
            #pragma unroll
            for (int j = 0; j < 8; j++) acc[i][j] += rp[j];
        }
        *(float4*)(cp + 0) = make_float4(acc[i][0], acc[i][1], acc[i][2], acc[i][3]);
        *(float4*)(cp + 4) = make_float4(acc[i][4], acc[i][5], acc[i][6], acc[i][7]);
    }
}

// ---------------------------------------------------------------------------
// RoPE: apply to q and k in place
// ---------------------------------------------------------------------------
__global__ __launch_bounds__(256) void rope_kernel(
    float* __restrict__ q, float* __restrict__ k, const float* __restrict__ freqs)
{
    int p = blockIdx.x * 256 + threadIdx.x;    // < NT * D/2
    int t = p >> 9;            // token
    int r = p & 511;
    int hh = r >> 6;           // head
    int i  = r & 63;           // rotary pair index
    int s  = t & (Sc - 1);     // position within sequence
    float f = freqs[s * 64 + i];
    float c = cosf(f), sn = sinf(f);
    size_t base = (size_t)t * Dc + hh * HDc + 2 * i;
    float e = q[base], o = q[base + 1];
    q[base] = e * c - o * sn; q[base + 1] = e * sn + o * c;
    e = k[base]; o = k[base + 1];
    k[base] = e * c - o * sn; k[base + 1] = e * sn + o * c;
}

// ---------------------------------------------------------------------------
// Flash attention: causal, 64 queries x 64 keys per tile, HD=128, fp32
// grid (S/64, H, B), 256 threads. Dynamic smem = 113 KB.
// ---------------------------------------------------------------------------
constexpr int FLASH_SMEM = (3 * 64 * 129 + 64 * 65) * 4;  // 115712 bytes

__global__ __launch_bounds__(256) void flash_kernel(
    const float* __restrict__ q, const float* __restrict__ k,
    const float* __restrict__ v, float* __restrict__ ao)
{
    extern __shared__ float sm[];
    float* Qs = sm;
    float* Ks = sm + 64 * 129;
    float* Vs = sm + 2 * 64 * 129;
    float* Ps = sm + 3 * 64 * 129;

    int tid = threadIdx.x;
    int tx = tid & 15, ty = tid >> 4;
    int qb = blockIdx.x, hh = blockIdx.y, b = blockIdx.z;

    const size_t qbase = ((size_t)(b * Sc + qb * 64)) * Dc + hh * HDc;
    const float scale = 0.08838834764831845f;  // 1/sqrt(128)

    // load Q tile (scaled)
    #pragma unroll
    for (int i = 0; i < 8; i++) {
        int li = tid + i * 256;
        int r = li >> 5, c = (li & 31) * 4;
        float4 val = *(const float4*)(q + qbase + (size_t)r * Dc + c);
        Qs[r * 129 + c + 0] = val.x * scale;
        Qs[r * 129 + c + 1] = val.y * scale;
        Qs[r * 129 + c + 2] = val.z * scale;
        Qs[r * 129 + c + 3] = val.w * scale;
    }

    float acc[4][8];
    float mrow[4], lrow[4];
    #pragma unroll
    for (int i = 0; i < 4; i++) {
        mrow[i] = -1e30f; lrow[i] = 0.f;
        #pragma unroll
        for (int c = 0; c < 8; c++) acc[i][c] = 0.f;
    }

    for (int kb = 0; kb <= qb; kb++) {
        const size_t kbase = ((size_t)(b * Sc + kb * 64)) * Dc + hh * HDc;
        #pragma unroll
        for (int i = 0; i < 8; i++) {
            int li = tid + i * 256;
            int r = li >> 5, c = (li & 31) * 4;
            float4 kv = *(const float4*)(k + kbase + (size_t)r * Dc + c);
            float4 vv = *(const float4*)(v + kbase + (size_t)r * Dc + c);
            Ks[r * 129 + c + 0] = kv.x; Ks[r * 129 + c + 1] = kv.y;
            Ks[r * 129 + c + 2] = kv.z; Ks[r * 129 + c + 3] = kv.w;
            Vs[r * 129 + c + 0] = vv.x; Vs[r * 129 + c + 1] = vv.y;
            Vs[r * 129 + c + 2] = vv.z; Vs[r * 129 + c + 3] = vv.w;
        }
        __syncthreads();

        // scores: s[i][j] = sum_d Qs[ty*4+i][d] * Ks[tx*4+j][d]
        float s[4][4];
        #pragma unroll
        for (int i = 0; i < 4; i++)
            #pragma unroll
            for (int j = 0; j < 4; j++) s[i][j] = 0.f;
        for (int d = 0; d < 128; d++) {
            float a0 = Qs[(ty * 4 + 0) * 129 + d];
            float a1 = Qs[(ty * 4 + 1) * 129 + d];
            float a2 = Qs[(ty * 4 + 2) * 129 + d];
            float a3 = Qs[(ty * 4 + 3) * 129 + d];
            float b0 = Ks[(tx * 4 + 0) * 129 + d];
            float b1 = Ks[(tx * 4 + 1) * 129 + d];
            float b2 = Ks[(tx * 4 + 2) * 129 + d];
            float b3 = Ks[(tx * 4 + 3) * 129 + d];
            s[0][0] = fmaf(a0, b0, s[0][0]); s[0][1] = fmaf(a0, b1, s[0][1]);
            s[0][2] = fmaf(a0, b2, s[0][2]); s[0][3] = fmaf(a0, b3, s[0][3]);
            s[1][0] = fmaf(a1, b0, s[1][0]); s[1][1] = fmaf(a1, b1, s[1][1]);
            s[1][2] = fmaf(a1, b2, s[1][2]); s[1][3] = fmaf(a1, b3, s[1][3]);
            s[2][0] = fmaf(a2, b0, s[2][0]); s[2][1] = fmaf(a2, b1, s[2][1]);
            s[2][2] = fmaf(a2, b2, s[2][2]); s[2][3] = fmaf(a2, b3, s[2][3]);
            s[3][0] = fmaf(a3, b0, s[3][0]); s[3][1] = fmaf(a3, b1, s[3][1]);
            s[3][2] = fmaf(a3, b2, s[3][2]); s[3][3] = fmaf(a3, b3, s[3][3]);
        }

        if (kb == qb) {
            #pragma unroll
            for (int i = 0; i < 4; i++)
                #pragma unroll
                for (int j = 0; j < 4; j++)
                    if (tx * 4 + j > ty * 4 + i) s[i][j] = -1e30f;
        }

        // online softmax update (rows owned by threads with same ty)
        #pragma unroll
        for (int i = 0; i < 4; i++) {
            float rm = fmaxf(fmaxf(s[i][0], s[i][1]), fmaxf(s[i][2], s[i][3]));
            #pragma unroll
            for (int m = 8; m >= 1; m >>= 1)
                rm = fmaxf(rm, __shfl_xor_sync(0xffffffffu, rm, m));
            float mn = fmaxf(mrow[i], rm);
            float p0 = __expf(s[i][0] - mn);
            float p1 = __expf(s[i][1] - mn);
            float p2 = __expf(s[i][2] - mn);
            float p3 = __expf(s[i][3] - mn);
            float rs = p0 + p1 + p2 + p3;
            #pragma unroll
            for (int m = 8; m >= 1; m >>= 1)
                rs += __shfl_xor_sync(0xffffffffu, rs, m);
            float sc = __expf(mrow[i] - mn);
            lrow[i] = lrow[i] * sc + rs;
            mrow[i] = mn;
            #pragma unroll
            for (int c = 0; c < 8; c++) acc[i][c] *= sc;
            float* pr = Ps + (ty * 4 + i) * 65 + tx * 4;
            pr[0] = p0; pr[1] = p1; pr[2] = p2; pr[3] = p3;
        }
        __syncthreads();

        // acc += P @ V
        for (int kk = 0; kk < 64; kk++) {
            float p0 = Ps[(ty * 4 + 0) * 65 + kk];
            float p1 = Ps[(ty * 4 + 1) * 65 + kk];
            float p2 = Ps[(ty * 4 + 2) * 65 + kk];
            float p3 = Ps[(ty * 4 + 3) * 65 + kk];
            #pragma unroll
            for (int c = 0; c < 8; c++) {
                float vv = Vs[kk * 129 + tx * 8 + c];
                acc[0][c] = fmaf(p0, vv, acc[0][c]);
                acc[1][c] = fmaf(p1, vv, acc[1][c]);
                acc[2][c] = fmaf(p2, vv, acc[2][c]);
                acc[3][c] = fmaf(p3, vv, acc[3][c]);
            }
        }
        __syncthreads();
    }

    #pragma unroll
    for (int i = 0; i < 4; i++) {
        float inv = 1.f / lrow[i];
        #pragma unroll
        for (int c = 0; c < 8; c++)
            ao[qbase + (size_t)(ty * 4 + i) * Dc + tx * 8 + c] = acc[i][c] * inv;
    }
}

// ---------------------------------------------------------------------------
// Gate: one warp per token. Computes logits, top-2, weights; builds expert
// lists via atomics (order-independent outputs -> deterministic results).
// ---------------------------------------------------------------------------
__global__ __launch_bounds__(256) void gate_kernel(
    const float* __restrict__ hn, const float* __restrict__ Wg,
    float* __restrict__ wslot, int* __restrict__ elist, int* __restrict__ ecount)
{
    int gtid = blockIdx.x * 256 + threadIdx.x;
    int t = gtid >> 5;
    int lane = gtid & 31;
    if (t >= NT) return;

    float acc[Ec];
    #pragma unroll
    for (int e = 0; e < Ec; e++) acc[e] = 0.f;
    const float* xr = hn + (size_t)t * Dc;
    for (int d = lane; d < Dc; d += 32) {
        float xv = xr[d];
        const float* wr = Wg + (size_t)d * Ec;
        #pragma unroll
        for (int e = 0; e < Ec; e++) acc[e] = fmaf(xv, wr[e], acc[e]);
    }
    #pragma unroll
    for (int e = 0; e < Ec; e++)
        #pragma unroll
        for (int m = 16; m >= 1; m >>= 1)
            acc[e] += __shfl_xor_sync(0xffffffffu, acc[e], m);

    if (lane == 0) {
        int e0 = 0; float l0 = acc[0];
        #pragma unroll
        for (int e = 1; e < Ec; e++) if (acc[e] > l0) { l0 = acc[e]; e0 = e; }
        int e1 = -1; float l1 = -3.4e38f;
        #pragma unroll
        for (int e = 0; e < Ec; e++) {
            if (e == e0) continue;
            if (acc[e] > l1) { l1 = acc[e]; e1 = e; }
        }
        float t1 = expf(l1 - l0);
        float w0 = 1.f / (1.f + t1);
        float w1 = t1 / (1.f + t1);
        wslot[2 * t]     = w0;
        wslot[2 * t + 1] = w1;
        int p0 = atomicAdd(&ecount[e0], 1);
        elist[e0 * NT + p0] = 2 * t;
        int p1 = atomicAdd(&ecount[e1], 1);
        elist[e1 * NT + p1] = 2 * t + 1;
    }
}

// ---------------------------------------------------------------------------
// MoE GEMM1 (gathered): act[slot, :] = silu(hn[token(slot), :] @ W1[e])
// grid (F/128, maxRowTiles=32, E)
// ---------------------------------------------------------------------------
__global__ __launch_bounds__(256) void moe_gemm1(
    const float* __restrict__ hn, const float* __restrict__ W1,
    float* __restrict__ act, const int* __restrict__ elist,
    const int* __restrict__ ecount)
{
    int e = blockIdx.z;
    int cnt = ecount[e];
    int rt = blockIdx.y * 128;
    if (rt >= cnt) return;
    int n0 = blockIdx.x * 128;

    __shared__ float As[8][136];
    __shared__ float Bs[8][128];
    int tid = threadIdx.x;
    int tx = tid & 15, ty = tid >> 4;
    int ar = tid >> 1, ac = (tid & 1) * 4;
    int br = tid >> 5, bc = (tid & 31) * 4;

    int aslot = (rt + ar < cnt) ? elist[e * NT + rt + ar] : -1;
    const float* Aptr = (aslot >= 0) ? hn + (size_t)(aslot >> 1) * Dc + ac : hn;
    const float* Bw = W1 + (size_t)e * Dc * Fc;
    const float* Bptr = Bw + (size_t)br * Fc + n0 + bc;

    float acc[8][8];
    #pragma unroll
    for (int i = 0; i < 8; i++)
        #pragma unroll
        for (int j = 0; j < 8; j++) acc[i][j] = 0.f;

    for (int k0 = 0; k0 < Dc; k0 += 8) {
        float4 av = (aslot >= 0) ? *(const float4*)(Aptr + k0)
                                 : make_float4(0.f, 0.f, 0.f, 0.f);
        float4 bv = *(const float4*)(Bptr + (size_t)k0 * Fc);
        As[ac + 0][ar] = av.x; As[ac + 1][ar] = av.y;
        As[ac + 2][ar] = av.z; As[ac + 3][ar] = av.w;
        *(float4*)&Bs[br][bc] = bv;
        __syncthreads();
        #pragma unroll
        for (int kk = 0; kk < 8; kk++) {
            float a[8], b[8];
            *(float4*)&a[0] = *(const float4*)&As[kk][ty * 8];
            *(float4*)&a[4] = *(const float4*)&As[kk][ty * 8 + 4];
            *(float4*)&b[0] = *(const float4*)&Bs[kk][tx * 8];
            *(float4*)&b[4] = *(const float4*)&Bs[kk][tx * 8 + 4];
            #pragma unroll
            for (int i = 0; i < 8; i++)
                #pragma unroll
                for (int j = 0; j < 8; j++)
                    acc[i][j] = fmaf(a[i], b[j], acc[i][j]);
        }
        __syncthreads();
    }

    #pragma unroll
    for (int i = 0; i < 8; i++) {
        int ridx = rt + ty * 8 + i;
        if (ridx < cnt) {
            int slot = elist[e * NT + ridx];
            float* op = act + (size_t)slot * Fc + n0 + tx * 8;
            #pragma unroll
            for (int j = 0; j < 8; j++) {
                float xv = acc[i][j];
                op[j] = xv / (1.f + expf(-xv));   // silu
            }
        }
    }
}

// ---------------------------------------------------------------------------
// MoE GEMM2 (gathered): moe_out[slot, :] = w[slot] * (act[slot, :] @ W2[e])
// grid (D/128=8, 32, E)
// ---------------------------------------------------------------------------
__global__ __launch_bounds__(256) void moe_gemm2(
    const float* __restrict__ act, const float* __restrict__ W2,
    float* __restrict__ moeout, const float* __restrict__ wslot,
    const int* __restrict__ elist, const int* __restrict__ ecount)
{
    int e = blockIdx.z;
    int cnt = ecount[e];
    int rt = blockIdx.y * 128;
    if (rt >= cnt) return;
    int n0 = blockIdx.x * 128;

    __shared__ float As[8][136];
    __shared__ float Bs[8][128];
    int tid = threadIdx.x;
    int tx = tid & 15, ty = tid >> 4;
    int ar = tid >> 1, ac = (tid & 1) * 4;
    int br = tid >> 5, bc = (tid & 31) * 4;

    int aslot = (rt + ar < cnt) ? elist[e * NT + rt + ar] : -1;
    const float* Aptr = (aslot >= 0) ? act + (size_t)aslot * Fc + ac : act;
    const float* Bw = W2 + (size_t)e * Fc * Dc;
    const float* Bptr = Bw + (size_t)br * Dc + n0 + bc;

    float acc[8][8];
    #pragma unroll
    for (int i = 0; i < 8; i++)
        #pragma unroll
        for (int j = 0; j < 8; j++) acc[i][j] = 0.f;

    for (int k0 = 0; k0 < Fc; k0 += 8) {
        float4 av = (aslot >= 0) ? *(const float4*)(Aptr + k0)
                                 : make_float4(0.f, 0.f, 0.f, 0.f);
        float4 bv = *(const float4*)(Bptr + (size_t)k0 * Dc);
        As[ac + 0][ar] = av.x; As[ac + 1][ar] = av.y;
        As[ac + 2][ar] = av.z; As[ac + 3][ar] = av.w;
        *(float4*)&Bs[br][bc] = bv;
        __syncthreads();
        #pragma unroll
        for (int kk = 0; kk < 8; kk++) {
            float a[8], b[8];
            *(float4*)&a[0] = *(const float4*)&As[kk][ty * 8];
            *(float4*)&a[4] = *(const float4*)&As[kk][ty * 8 + 4];
            *(float4*)&b[0] = *(const float4*)&Bs[kk][tx * 8];
            *(float4*)&b[4] = *(const float4*)&Bs[kk][tx * 8 + 4];
            #pragma unroll
            for (int i = 0; i < 8; i++)
                #pragma unroll
                for (int j = 0; j < 8; j++)
                    acc[i][j] = fmaf(a[i], b[j], acc[i][j]);
        }
        __syncthreads();
    }

    #pragma unroll
    for (int i = 0; i < 8; i++) {
        int ridx = rt + ty * 8 + i;
        if (ridx < cnt) {
            int slot = elist[e * NT + ridx];
            float w = wslot[slot];
            float* op = moeout + (size_t)slot * Dc + n0 + tx * 8;
            #pragma unroll
            for (int j = 0; j < 8; j++) op[j] = acc[i][j] * w;
        }
    }
}

// ---------------------------------------------------------------------------
// Final combine: out = h + moe(slot0) + moe(slot1)
// ---------------------------------------------------------------------------
__global__ __launch_bounds__(256) void combine_kernel(
    const float* __restrict__ h, const float* __restrict__ moeout,
    float* __restrict__ out)
{
    size_t i = (size_t)blockIdx.x * 256 + threadIdx.x;
    size_t t = i >> 10, d = i & 1023;
    out[i] = h[i] + moeout[(2 * t) * (size_t)Dc + d]
                  + moeout[(2 * t + 1) * (size_t)Dc + d];
}

// ---------------------------------------------------------------------------
// Launch
// ---------------------------------------------------------------------------
extern "C" void kernel_launch(void* const* d_in, const int* in_sizes, int n_in,
                              void* d_out, int out_size)
{
    const float* x     = (const float*)d_in[0];
    const float* freqs = (const float*)d_in[1];
    const float* g1    = (const float*)d_in[2];
    const float* b1    = (const float*)d_in[3];
    const float* g2    = (const float*)d_in[4];
    const float* b2    = (const float*)d_in[5];
    const float* Wq    = (const float*)d_in[6];
    const float* Wdkv  = (const float*)d_in[7];
    const float* Wuk   = (const float*)d_in[8];
    const float* Wuv   = (const float*)d_in[9];
    const float* Wo    = (const float*)d_in[10];
    const float* Wg    = (const float*)d_in[11];
    const float* W1    = (const float*)d_in[12];
    const float* W2    = (const float*)d_in[13];
    float* out = (float*)d_out;

    void* bufp = nullptr;
    cudaGetSymbolAddress(&bufp, g_buf);
    float* buf   = (float*)bufp;
    float* xn    = buf + OFF_XN;
    float* qb_   = buf + OFF_Q;
    float* kb_   = buf + OFF_K;
    float* vb_   = buf + OFF_V;
    float* lat   = buf + OFF_LAT;
    float* ao    = buf + OFF_AO;
    float* h     = buf + OFF_H;
    float* hn    = buf + OFF_HN;
    float* act   = buf + OFF_ACT;
    float* moeo  = buf + OFF_MOE;
    float* wslot = buf + OFF_WSLOT;
    int*   elist = (int*)(buf + OFF_ELIST);
    int*   ecnt  = (int*)(buf + OFF_ECNT);

    cudaFuncSetAttribute(flash_kernel,
                         cudaFuncAttributeMaxDynamicSharedMemorySize, FLASH_SMEM);

    reset_kernel<<<1, 32>>>(ecnt);
    ln_kernel<<<NT, 256>>>(x, g1, b1, xn);

    sgemm128<<<dim3(Dc / 128, NT / 128), 256>>>(xn, Wq,   nullptr, qb_, NT, Dc, Dc);
    sgemm128<<<dim3(Lc / 128, NT / 128), 256>>>(xn, Wdkv, nullptr, lat, NT, Dc, Lc);
    sgemm128<<<dim3(Dc / 128, NT / 128), 256>>>(lat, Wuk, nullptr, kb_, NT, Lc, Dc);
    sgemm128<<<dim3(Dc / 128, NT / 128), 256>>>(lat, Wuv, nullptr, vb_, NT, Lc, Dc);

    rope_kernel<<<(NT * (Dc / 2)) / 256, 256>>>(qb_, kb_, freqs);

    flash_kernel<<<dim3(Sc / 64, Hc, Bc), 256, FLASH_SMEM>>>(qb_, kb_, vb_, ao);

    sgemm128<<<dim3(Dc / 128, NT / 128), 256>>>(ao, Wo, x, h, NT, Dc, Dc);

    ln_kernel<<<NT, 256>>>(h, g2, b2, hn);

    gate_kernel<<<(NT * 32) / 256, 256>>>(hn, Wg, wslot, elist, ecnt);

    moe_gemm1<<<dim3(Fc / 128, NT / 128, Ec), 256>>>(hn, W1, act, elist, ecnt);
    moe_gemm2<<<dim3(Dc / 128, NT / 128, Ec), 256>>>(act, W2, moeo, wslot, elist, ecnt);

    combine_kernel<<<(NT * Dc) / 256, 256>>>(h, moeo, out);
}

// round 6
// speedup vs baseline: 1.7836x; 1.7836x over previous
#include <cuda_runtime.h>
#include <cuda_bf16.h>
#include <math.h>
#include <stdint.h>

constexpr int Bc  = 2;
constexpr int Sc  = 2048;
constexpr int Dc  = 1024;
constexpr int Lc  = 512;
constexpr int Hc  = 8;
constexpr int HDc = 128;
constexpr int Ec  = 8;
constexpr int Fc  = 4096;
constexpr int NT  = Bc * Sc;

constexpr size_t OFF_XN    = 0;
constexpr size_t OFF_Q     = OFF_XN    + (size_t)NT * Dc;
constexpr size_t OFF_K     = OFF_Q     + (size_t)NT * Dc;
constexpr size_t OFF_V     = OFF_K     + (size_t)NT * Dc;
constexpr size_t OFF_LAT   = OFF_V     + (size_t)NT * Dc;
constexpr size_t OFF_AO    = OFF_LAT   + (size_t)NT * Lc;
constexpr size_t OFF_H     = OFF_AO    + (size_t)NT * Dc;
constexpr size_t OFF_HN    = OFF_H     + (size_t)NT * Dc;
constexpr size_t OFF_ACT   = OFF_HN    + (size_t)NT * Dc;
constexpr size_t OFF_MOE   = OFF_ACT   + (size_t)2 * NT * Fc;
constexpr size_t OFF_WSLOT = OFF_MOE   + (size_t)2 * NT * Dc;
constexpr size_t OFF_ELIST = OFF_WSLOT + (size_t)2 * NT;
constexpr size_t OFF_ECNT  = OFF_ELIST + (size_t)Ec * NT;
constexpr size_t BUF_TOTAL = OFF_ECNT + 64;

__device__ float g_buf[BUF_TOTAL];

__global__ void reset_kernel(int* ecount) {
    if (threadIdx.x < Ec) ecount[threadIdx.x] = 0;
}

__global__ __launch_bounds__(256) void ln_kernel(
    const float* __restrict__ x, const float* __restrict__ g,
    const float* __restrict__ b, float* __restrict__ y)
{
    int t = blockIdx.x;
    int tid = threadIdx.x;
    const float* xr = x + (size_t)t * Dc;
    float s = 0.f, s2 = 0.f;
    #pragma unroll
    for (int i = tid; i < Dc; i += 256) { float v = xr[i]; s += v; s2 += v * v; }
    __shared__ float sh[2][256];
    sh[0][tid] = s; sh[1][tid] = s2;
    __syncthreads();
    for (int st = 128; st > 0; st >>= 1) {
        if (tid < st) { sh[0][tid] += sh[0][tid + st]; sh[1][tid] += sh[1][tid + st]; }
        __syncthreads();
    }
    float mu   = sh[0][0] * (1.f / Dc);
    float var  = sh[1][0] * (1.f / Dc) - mu * mu;
    float rstd = rsqrtf(var + 1e-5f);
    float* yr = y + (size_t)t * Dc;
    #pragma unroll
    for (int i = tid; i < Dc; i += 256)
        yr[i] = (xr[i] - mu) * rstd * g[i] + b[i];
}

__device__ __forceinline__ void cp16(uint32_t dst, const void* src, int srcsize) {
    asm volatile("cp.async.cg.shared.global [%0], [%1], 16, %2;"
                 :: "r"(dst), "l"(src), "r"(srcsize));
}
__device__ __forceinline__ void cp_commit() {
    asm volatile("cp.async.commit_group;");
}
template <int N>
__device__ __forceinline__ void cp_wait() {
    asm volatile("cp.async.wait_group %0;" :: "n"(N));
}

// split a pair of fp32 into bf16x2 hi + bf16x2 lo  (first arg in low half)
__device__ __forceinline__ void split2(float x0, float x1, uint32_t& hi, uint32_t& lo) {
    uint32_t h;
    asm("cvt.rn.bf16x2.f32 %0, %1, %2;" : "=r"(h) : "f"(x1), "f"(x0));
    float h0 = __uint_as_float(h << 16);
    float h1 = __uint_as_float(h & 0xffff0000u);
    uint32_t l;
    asm("cvt.rn.bf16x2.f32 %0, %1, %2;" : "=r"(l) : "f"(x1 - h1), "f"(x0 - h0));
    hi = h; lo = l;
}

__device__ __forceinline__ void mma_bf16(float* d, const uint32_t* a, const uint32_t* b) {
    asm volatile(
        "mma.sync.aligned.m16n8k16.row.col.f32.bf16.bf16.f32 "
        "{%0,%1,%2,%3}, {%4,%5,%6,%7}, {%8,%9}, {%0,%1,%2,%3};"
        : "+f"(d[0]), "+f"(d[1]), "+f"(d[2]), "+f"(d[3])
        : "r"(a[0]), "r"(a[1]), "r"(a[2]), "r"(a[3]), "r"(b[0]), "r"(b[1]));
}

constexpr int APAD = 20;
constexpr int BPAD = 132;

// 128x128 block tile, BK=16, double-buffered cp.async, bf16 split 3-mma.
// 8 warps: 2(M) x 4(N); warp tile 64x32.
// EPI: 0 none, 1 +resid, 2 silu, 3 *wslot.  GATHER: rows via elist.
template <int EPI, bool GATHER>
__global__ __launch_bounds__(256) void tgemm_kernel(
    const float* __restrict__ A, const float* __restrict__ B,
    const float* __restrict__ resid, float* __restrict__ C,
    int M, int K, int N,
    const int* __restrict__ elist, const int* __restrict__ ecount,
    const float* __restrict__ wslot, int ashift, size_t bExpertStride)
{
    __shared__ float As[2][128][APAD];
    __shared__ float Bs[2][16][BPAD];

    const int tid  = threadIdx.x;
    const int warp = tid >> 5;
    const int lane = tid & 31;
    const int wy = warp & 1;
    const int wx = warp >> 1;
    const int mW = wy * 64;
    const int nW = wx * 32;
    const int l4 = lane >> 2;
    const int lm = lane & 3;

    const int n0 = blockIdx.x * 128;

    int e = 0, cnt = 0, rt = 0, m0 = 0;
    const float* Bbase = B;
    if (GATHER) {
        e = blockIdx.z;
        cnt = ecount[e];
        rt = blockIdx.y * 128;
        if (rt >= cnt) return;
        Bbase = B + (size_t)e * bExpertStride;
    } else {
        m0 = blockIdx.y * 128;
    }

    const int arow  = tid >> 1;
    const int acolg = (tid & 1) * 8;
    const int brow  = tid >> 4;
    const int bcol  = (tid & 15) * 8;

    const float* aptr;
    int asz = 16;
    if (GATHER) {
        int g = rt + arow;
        bool valid = g < cnt;
        int slot = valid ? elist[e * NT + g] : 0;
        aptr = A + (size_t)(slot >> ashift) * K + acolg;
        asz = valid ? 16 : 0;
    } else {
        aptr = A + (size_t)(m0 + arow) * K + acolg;
    }
    const float* bptr = Bbase + n0 + bcol;

    uint32_t dA0 = (uint32_t)__cvta_generic_to_shared(&As[0][arow][acolg]);
    uint32_t dA1 = dA0 + 16;
    uint32_t dB0 = (uint32_t)__cvta_generic_to_shared(&Bs[0][brow][bcol]);
    uint32_t dB1 = dB0 + 16;
    const uint32_t bufStrideA = 128 * APAD * 4;
    const uint32_t bufStrideB = 16 * BPAD * 4;

    float acc[4][4][4];
    #pragma unroll
    for (int i = 0; i < 4; i++)
        #pragma unroll
        for (int j = 0; j < 4; j++)
            #pragma unroll
            for (int c = 0; c < 4; c++) acc[i][j][c] = 0.f;

    const int KT = K >> 4;

    cp16(dA0, aptr + 0, asz);
    cp16(dA1, aptr + 4, asz);
    cp16(dB0, bptr + (size_t)brow * N, 16);
    cp16(dB1, bptr + (size_t)brow * N + 4, 16);
    cp_commit();

    int buf = 0;
    for (int kt = 0; kt < KT; kt++) {
        if (kt + 1 < KT) {
            int k0 = (kt + 1) * 16;
            int nb = buf ^ 1;
            cp16(dA0 + nb * bufStrideA, aptr + k0,     asz);
            cp16(dA1 + nb * bufStrideA, aptr + k0 + 4, asz);
            cp16(dB0 + nb * bufStrideB, bptr + (size_t)(k0 + brow) * N,     16);
            cp16(dB1 + nb * bufStrideB, bptr + (size_t)(k0 + brow) * N + 4, 16);
            cp_commit();
            cp_wait<1>();
        } else {
            cp_wait<0>();
        }
        __syncthreads();

        uint32_t ahi[4][4], alo[4][4];
        #pragma unroll
        for (int mi = 0; mi < 4; mi++) {
            int r = mW + mi * 16 + l4;
            float2 p00 = *(const float2*)&As[buf][r    ][2 * lm];
            float2 p10 = *(const float2*)&As[buf][r + 8][2 * lm];
            float2 p01 = *(const float2*)&As[buf][r    ][2 * lm + 8];
            float2 p11 = *(const float2*)&As[buf][r + 8][2 * lm + 8];
            split2(p00.x, p00.y, ahi[mi][0], alo[mi][0]);
            split2(p10.x, p10.y, ahi[mi][1], alo[mi][1]);
            split2(p01.x, p01.y, ahi[mi][2], alo[mi][2]);
            split2(p11.x, p11.y, ahi[mi][3], alo[mi][3]);
        }
        #pragma unroll
        for (int ni = 0; ni < 4; ni++) {
            int c = nW + ni * 8 + l4;
            float b00 = Bs[buf][2 * lm    ][c];
            float b01 = Bs[buf][2 * lm + 1][c];
            float b08 = Bs[buf][2 * lm + 8][c];
            float b09 = Bs[buf][2 * lm + 9][c];
            uint32_t bhi[2], blo[2];
            split2(b00, b01, bhi[0], blo[0]);
            split2(b08, b09, bhi[1], blo[1]);
            #pragma unroll
            for (int mi = 0; mi < 4; mi++) {
                mma_bf16(acc[mi][ni], ahi[mi], bhi);
                mma_bf16(acc[mi][ni], ahi[mi], blo);
                mma_bf16(acc[mi][ni], alo[mi], bhi);
            }
        }
        __syncthreads();
        buf ^= 1;
    }

    #pragma unroll
    for (int mi = 0; mi < 4; mi++) {
        int r0 = mW + mi * 16 + l4;
        int r1 = r0 + 8;
        size_t crow0, crow1;
        bool v0 = true, v1 = true;
        float w0 = 1.f, w1 = 1.f;
        if (GATHER) {
            int g0 = rt + r0, g1 = rt + r1;
            v0 = g0 < cnt; v1 = g1 < cnt;
            int s0 = v0 ? elist[e * NT + g0] : 0;
            int s1 = v1 ? elist[e * NT + g1] : 0;
            crow0 = (size_t)s0 * N;
            crow1 = (size_t)s1 * N;
            if (EPI == 3) { w0 = v0 ? wslot[s0] : 0.f; w1 = v1 ? wslot[s1] : 0.f; }
        } else {
            crow0 = (size_t)(m0 + r0) * N;
            crow1 = (size_t)(m0 + r1) * N;
        }
        #pragma unroll
        for (int ni = 0; ni < 4; ni++) {
            int col = n0 + nW + ni * 8 + 2 * lm;     // FIXED: include n0
            float x0 = acc[mi][ni][0], x1 = acc[mi][ni][1];
            float x2 = acc[mi][ni][2], x3 = acc[mi][ni][3];
            if (EPI == 1) {
                const float* rp0 = resid + crow0 + col;
                const float* rp1 = resid + crow1 + col;
                x0 += rp0[0]; x1 += rp0[1];
                x2 += rp1[0]; x3 += rp1[1];
            } else if (EPI == 2) {
                x0 = x0 / (1.f + __expf(-x0));
                x1 = x1 / (1.f + __expf(-x1));
                x2 = x2 / (1.f + __expf(-x2));
                x3 = x3 / (1.f + __expf(-x3));
            } else if (EPI == 3) {
                x0 *= w0; x1 *= w0; x2 *= w1; x3 *= w1;
            }
            if (v0) *(float2*)&C[crow0 + col] = make_float2(x0, x1);
            if (v1) *(float2*)&C[crow1 + col] = make_float2(x2, x3);
        }
    }
}

__global__ __launch_bounds__(256) void rope_kernel(
    float* __restrict__ q, float* __restrict__ k, const float* __restrict__ freqs)
{
    int p = blockIdx.x * 256 + threadIdx.x;
    int t = p >> 9;
    int r = p & 511;
    int hh = r >> 6;
    int i  = r & 63;
    int s  = t & (Sc - 1);
    float f = freqs[s * 64 + i];
    float c = cosf(f), sn = sinf(f);
    size_t base = (size_t)t * Dc + hh * HDc + 2 * i;
    float e = q[base], o = q[base + 1];
    q[base] = e * c - o * sn; q[base + 1] = e * sn + o * c;
    e = k[base]; o = k[base + 1];
    k[base] = e * c - o * sn; k[base + 1] = e * sn + o * c;
}

constexpr int FLASH_SMEM = (3 * 64 * 129 + 64 * 65) * 4;

__global__ __launch_bounds__(256) void flash_kernel(
    const float* __restrict__ q, const float* __restrict__ k,
    const float* __restrict__ v, float* __restrict__ ao)
{
    extern __shared__ float sm[];
    float* Qs = sm;
    float* Ks = sm + 64 * 129;
    float* Vs = sm + 2 * 64 * 129;
    float* Ps = sm + 3 * 64 * 129;

    int tid = threadIdx.x;
    int tx = tid & 15, ty = tid >> 4;
    int qb = blockIdx.x, hh = blockIdx.y, b = blockIdx.z;

    const size_t qbase = ((size_t)(b * Sc + qb * 64)) * Dc + hh * HDc;
    const float scale = 0.08838834764831845f;

    #pragma unroll
    for (int i = 0; i < 8; i++) {
        int li = tid + i * 256;
        int r = li >> 5, c = (li & 31) * 4;
        float4 val = *(const float4*)(q + qbase + (size_t)r * Dc + c);
        Qs[r * 129 + c + 0] = val.x * scale;
        Qs[r * 129 + c + 1] = val.y * scale;
        Qs[r * 129 + c + 2] = val.z * scale;
        Qs[r * 129 + c + 3] = val.w * scale;
    }

    float acc[4][8];
    float mrow[4], lrow[4];
    #pragma unroll
    for (int i = 0; i < 4; i++) {
        mrow[i] = -1e30f; lrow[i] = 0.f;
        #pragma unroll
        for (int c = 0; c < 8; c++) acc[i][c] = 0.f;
    }

    for (int kb = 0; kb <= qb; kb++) {
        const size_t kbase = ((size_t)(b * Sc + kb * 64)) * Dc + hh * HDc;
        #pragma unroll
        for (int i = 0; i < 8; i++) {
            int li = tid + i * 256;
            int r = li >> 5, c = (li & 31) * 4;
            float4 kv = *(const float4*)(k + kbase + (size_t)r * Dc + c);
            float4 vv = *(const float4*)(v + kbase + (size_t)r * Dc + c);
            Ks[r * 129 + c + 0] = kv.x; Ks[r * 129 + c + 1] = kv.y;
            Ks[r * 129 + c + 2] = kv.z; Ks[r * 129 + c + 3] = kv.w;
            Vs[r * 129 + c + 0] = vv.x; Vs[r * 129 + c + 1] = vv.y;
            Vs[r * 129 + c + 2] = vv.z; Vs[r * 129 + c + 3] = vv.w;
        }
        __syncthreads();

        float s[4][4];
        #pragma unroll
        for (int i = 0; i < 4; i++)
            #pragma unroll
            for (int j = 0; j < 4; j++) s[i][j] = 0.f;
        for (int d = 0; d < 128; d++) {
            float a0 = Qs[(ty * 4 + 0) * 129 + d];
            float a1 = Qs[(ty * 4 + 1) * 129 + d];
            float a2 = Qs[(ty * 4 + 2) * 129 + d];
            float a3 = Qs[(ty * 4 + 3) * 129 + d];
            float b0 = Ks[(tx * 4 + 0) * 129 + d];
            float b1 = Ks[(tx * 4 + 1) * 129 + d];
            float b2 = Ks[(tx * 4 + 2) * 129 + d];
            float b3 = Ks[(tx * 4 + 3) * 129 + d];
            s[0][0] = fmaf(a0, b0, s[0][0]); s[0][1] = fmaf(a0, b1, s[0][1]);
            s[0][2] = fmaf(a0, b2, s[0][2]); s[0][3] = fmaf(a0, b3, s[0][3]);
            s[1][0] = fmaf(a1, b0, s[1][0]); s[1][1] = fmaf(a1, b1, s[1][1]);
            s[1][2] = fmaf(a1, b2, s[1][2]); s[1][3] = fmaf(a1, b3, s[1][3]);
            s[2][0] = fmaf(a2, b0, s[2][0]); s[2][1] = fmaf(a2, b1, s[2][1]);
            s[2][2] = fmaf(a2, b2, s[2][2]); s[2][3] = fmaf(a2, b3, s[2][3]);
            s[3][0] = fmaf(a3, b0, s[3][0]); s[3][1] = fmaf(a3, b1, s[3][1]);
            s[3][2] = fmaf(a3, b2, s[3][2]); s[3][3] = fmaf(a3, b3, s[3][3]);
        }

        if (kb == qb) {
            #pragma unroll
            for (int i = 0; i < 4; i++)
                #pragma unroll
                for (int j = 0; j < 4; j++)
                    if (tx * 4 + j > ty * 4 + i) s[i][j] = -1e30f;
        }

        #pragma unroll
        for (int i = 0; i < 4; i++) {
            float rm = fmaxf(fmaxf(s[i][0], s[i][1]), fmaxf(s[i][2], s[i][3]));
            #pragma unroll
            for (int m = 8; m >= 1; m >>= 1)
                rm = fmaxf(rm, __shfl_xor_sync(0xffffffffu, rm, m));
            float mn = fmaxf(mrow[i], rm);
            float p0 = __expf(s[i][0] - mn);
            float p1 = __expf(s[i][1] - mn);
            float p2 = __expf(s[i][2] - mn);
            float p3 = __expf(s[i][3] - mn);
            float rs = p0 + p1 + p2 + p3;
            #pragma unroll
            for (int m = 8; m >= 1; m >>= 1)
                rs += __shfl_xor_sync(0xffffffffu, rs, m);
            float sc = __expf(mrow[i] - mn);
            lrow[i] = lrow[i] * sc + rs;
            mrow[i] = mn;
            #pragma unroll
            for (int c = 0; c < 8; c++) acc[i][c] *= sc;
            float* pr = Ps + (ty * 4 + i) * 65 + tx * 4;
            pr[0] = p0; pr[1] = p1; pr[2] = p2; pr[3] = p3;
        }
        __syncthreads();

        for (int kk = 0; kk < 64; kk++) {
            float p0 = Ps[(ty * 4 + 0) * 65 + kk];
            float p1 = Ps[(ty * 4 + 1) * 65 + kk];
            float p2 = Ps[(ty * 4 + 2) * 65 + kk];
            float p3 = Ps[(ty * 4 + 3) * 65 + kk];
            #pragma unroll
            for (int c = 0; c < 8; c++) {
                float vv = Vs[kk * 129 + tx * 8 + c];
                acc[0][c] = fmaf(p0, vv, acc[0][c]);
                acc[1][c] = fmaf(p1, vv, acc[1][c]);
                acc[2][c] = fmaf(p2, vv, acc[2][c]);
                acc[3][c] = fmaf(p3, vv, acc[3][c]);
            }
        }
        __syncthreads();
    }

    #pragma unroll
    for (int i = 0; i < 4; i++) {
        float inv = 1.f / lrow[i];
        #pragma unroll
        for (int c = 0; c < 8; c++)
            ao[qbase + (size_t)(ty * 4 + i) * Dc + tx * 8 + c] = acc[i][c] * inv;
    }
}

__global__ __launch_bounds__(256) void gate_kernel(
    const float* __restrict__ hn, const float* __restrict__ Wg,
    float* __restrict__ wslot, int* __restrict__ elist, int* __restrict__ ecount)
{
    int gtid = blockIdx.x * 256 + threadIdx.x;
    int t = gtid >> 5;
    int lane = gtid & 31;
    if (t >= NT) return;

    float acc[Ec];
    #pragma unroll
    for (int e = 0; e < Ec; e++) acc[e] = 0.f;
    const float* xr = hn + (size_t)t * Dc;
    for (int d = lane; d < Dc; d += 32) {
        float xv = xr[d];
        const float* wr = Wg + (size_t)d * Ec;
        #pragma unroll
        for (int e = 0; e < Ec; e++) acc[e] = fmaf(xv, wr[e], acc[e]);
    }
    #pragma unroll
    for (int e = 0; e < Ec; e++)
        #pragma unroll
        for (int m = 16; m >= 1; m >>= 1)
            acc[e] += __shfl_xor_sync(0xffffffffu, acc[e], m);

    if (lane == 0) {
        int e0 = 0; float l0 = acc[0];
        #pragma unroll
        for (int e = 1; e < Ec; e++) if (acc[e] > l0) { l0 = acc[e]; e0 = e; }
        int e1 = -1; float l1 = -3.4e38f;
        #pragma unroll
        for (int e = 0; e < Ec; e++) {
            if (e == e0) continue;
            if (acc[e] > l1) { l1 = acc[e]; e1 = e; }
        }
        float t1 = expf(l1 - l0);
        float w0 = 1.f / (1.f + t1);
        float w1 = t1 / (1.f + t1);
        wslot[2 * t]     = w0;
        wslot[2 * t + 1] = w1;
        int p0 = atomicAdd(&ecount[e0], 1);
        elist[e0 * NT + p0] = 2 * t;
        int p1 = atomicAdd(&ecount[e1], 1);
        elist[e1 * NT + p1] = 2 * t + 1;
    }
}

__global__ __launch_bounds__(256) void combine_kernel(
    const float* __restrict__ h, const float* __restrict__ moeout,
    float* __restrict__ out)
{
    size_t i = (size_t)blockIdx.x * 256 + threadIdx.x;
    size_t t = i >> 10, d = i & 1023;
    out[i] = h[i] + moeout[(2 * t) * (size_t)Dc + d]
                  + moeout[(2 * t + 1) * (size_t)Dc + d];
}

extern "C" void kernel_launch(void* const* d_in, const int* in_sizes, int n_in,
                              void* d_out, int out_size)
{
    const float* x     = (const float*)d_in[0];
    const float* freqs = (const float*)d_in[1];
    const float* g1    = (const float*)d_in[2];
    const float* b1    = (const float*)d_in[3];
    const float* g2    = (const float*)d_in[4];
    const float* b2    = (const float*)d_in[5];
    const float* Wq    = (const float*)d_in[6];
    const float* Wdkv  = (const float*)d_in[7];
    const float* Wuk   = (const float*)d_in[8];
    const float* Wuv   = (const float*)d_in[9];
    const float* Wo    = (const float*)d_in[10];
    const float* Wg    = (const float*)d_in[11];
    const float* W1    = (const float*)d_in[12];
    const float* W2    = (const float*)d_in[13];
    float* out = (float*)d_out;

    void* bufp = nullptr;
    cudaGetSymbolAddress(&bufp, g_buf);
    float* buf   = (float*)bufp;
    float* xn    = buf + OFF_XN;
    float* qb_   = buf + OFF_Q;
    float* kb_   = buf + OFF_K;
    float* vb_   = buf + OFF_V;
    float* lat   = buf + OFF_LAT;
    float* ao    = buf + OFF_AO;
    float* h     = buf + OFF_H;
    float* hn    = buf + OFF_HN;
    float* act   = buf + OFF_ACT;
    float* moeo  = buf + OFF_MOE;
    float* wslot = buf + OFF_WSLOT;
    int*   elist = (int*)(buf + OFF_ELIST);
    int*   ecnt  = (int*)(buf + OFF_ECNT);

    cudaFuncSetAttribute(flash_kernel,
                         cudaFuncAttributeMaxDynamicSharedMemorySize, FLASH_SMEM);

    reset_kernel<<<1, 32>>>(ecnt);
    ln_kernel<<<NT, 256>>>(x, g1, b1, xn);

    tgemm_kernel<0, false><<<dim3(Dc / 128, NT / 128), 256>>>(
        xn, Wq, nullptr, qb_, NT, Dc, Dc, nullptr, nullptr, nullptr, 0, 0);
    tgemm_kernel<0, false><<<dim3(Lc / 128, NT / 128), 256>>>(
        xn, Wdkv, nullptr, lat, NT, Dc, Lc, nullptr, nullptr, nullptr, 0, 0);
    tgemm_kernel<0, false><<<dim3(Dc / 128, NT / 128), 256>>>(
        lat, Wuk, nullptr, kb_, NT, Lc, Dc, nullptr, nullptr, nullptr, 0, 0);
    tgemm_kernel<0, false><<<dim3(Dc / 128, NT / 128), 256>>>(
        lat, Wuv, nullptr, vb_, NT, Lc, Dc, nullptr, nullptr, nullptr, 0, 0);

    rope_kernel<<<(NT * (Dc / 2)) / 256, 256>>>(qb_, kb_, freqs);

    flash_kernel<<<dim3(Sc / 64, Hc, Bc), 256, FLASH_SMEM>>>(qb_, kb_, vb_, ao);

    tgemm_kernel<1, false><<<dim3(Dc / 128, NT / 128), 256>>>(
        ao, Wo, x, h, NT, Dc, Dc, nullptr, nullptr, nullptr, 0, 0);

    ln_kernel<<<NT, 256>>>(h, g2, b2, hn);

    gate_kernel<<<(NT * 32) / 256, 256>>>(hn, Wg, wslot, elist, ecnt);

    tgemm_kernel<2, true><<<dim3(Fc / 128, NT / 128, Ec), 256>>>(
        hn, W1, nullptr, act, 0, Dc, Fc, elist, ecnt, nullptr, 1, (size_t)Dc * Fc);
    tgemm_kernel<3, true><<<dim3(Dc / 128, NT / 128, Ec), 256>>>(
        act, W2, nullptr, moeo, 0, Fc, Dc, elist, ecnt, wslot, 0, (size_t)Fc * Dc);

    combine_kernel<<<(NT * Dc) / 256, 256>>>(h, moeo, out);
}

// round 7
// speedup vs baseline: 2.5008x; 1.4021x over previous
#include <cuda_runtime.h>
#include <cuda_bf16.h>
#include <math.h>
#include <stdint.h>

constexpr int Bc  = 2;
constexpr int Sc  = 2048;
constexpr int Dc  = 1024;
constexpr int Lc  = 512;
constexpr int Hc  = 8;
constexpr int HDc = 128;
constexpr int Ec  = 8;
constexpr int Fc  = 4096;
constexpr int NT  = Bc * Sc;

constexpr size_t OFF_XN    = 0;
constexpr size_t OFF_Q     = OFF_XN    + (size_t)NT * Dc;
constexpr size_t OFF_K     = OFF_Q     + (size_t)NT * Dc;
constexpr size_t OFF_V     = OFF_K     + (size_t)NT * Dc;
constexpr size_t OFF_LAT   = OFF_V     + (size_t)NT * Dc;
constexpr size_t OFF_AO    = OFF_LAT   + (size_t)NT * Lc;
constexpr size_t OFF_H     = OFF_AO    + (size_t)NT * Dc;
constexpr size_t OFF_HN    = OFF_H     + (size_t)NT * Dc;
constexpr size_t OFF_ACT   = OFF_HN    + (size_t)NT * Dc;
constexpr size_t OFF_MOE   = OFF_ACT   + (size_t)2 * NT * Fc;
constexpr size_t OFF_WSLOT = OFF_MOE   + (size_t)2 * NT * Dc;
constexpr size_t OFF_ELIST = OFF_WSLOT + (size_t)2 * NT;
constexpr size_t OFF_ECNT  = OFF_ELIST + (size_t)Ec * NT;
constexpr size_t BUF_TOTAL = OFF_ECNT + 64;

__device__ float g_buf[BUF_TOTAL];

__global__ void reset_kernel(int* ecount) {
    if (threadIdx.x < Ec) ecount[threadIdx.x] = 0;
}

__global__ __launch_bounds__(256) void ln_kernel(
    const float* __restrict__ x, const float* __restrict__ g,
    const float* __restrict__ b, float* __restrict__ y)
{
    int t = blockIdx.x;
    int tid = threadIdx.x;
    const float* xr = x + (size_t)t * Dc;
    float s = 0.f, s2 = 0.f;
    #pragma unroll
    for (int i = tid; i < Dc; i += 256) { float v = xr[i]; s += v; s2 += v * v; }
    __shared__ float sh[2][256];
    sh[0][tid] = s; sh[1][tid] = s2;
    __syncthreads();
    for (int st = 128; st > 0; st >>= 1) {
        if (tid < st) { sh[0][tid] += sh[0][tid + st]; sh[1][tid] += sh[1][tid + st]; }
        __syncthreads();
    }
    float mu   = sh[0][0] * (1.f / Dc);
    float var  = sh[1][0] * (1.f / Dc) - mu * mu;
    float rstd = rsqrtf(var + 1e-5f);
    float* yr = y + (size_t)t * Dc;
    #pragma unroll
    for (int i = tid; i < Dc; i += 256)
        yr[i] = (xr[i] - mu) * rstd * g[i] + b[i];
}

__device__ __forceinline__ void cp16(uint32_t dst, const void* src, int srcsize) {
    asm volatile("cp.async.cg.shared.global [%0], [%1], 16, %2;"
                 :: "r"(dst), "l"(src), "r"(srcsize));
}
__device__ __forceinline__ void cp_commit() {
    asm volatile("cp.async.commit_group;");
}
template <int N>
__device__ __forceinline__ void cp_wait() {
    asm volatile("cp.async.wait_group %0;" :: "n"(N));
}

__device__ __forceinline__ void split2(float x0, float x1, uint32_t& hi, uint32_t& lo) {
    uint32_t h;
    asm("cvt.rn.bf16x2.f32 %0, %1, %2;" : "=r"(h) : "f"(x1), "f"(x0));
    float h0 = __uint_as_float(h << 16);
    float h1 = __uint_as_float(h & 0xffff0000u);
    uint32_t l;
    asm("cvt.rn.bf16x2.f32 %0, %1, %2;" : "=r"(l) : "f"(x1 - h1), "f"(x0 - h0));
    hi = h; lo = l;
}

__device__ __forceinline__ void mma_bf16(float* d, const uint32_t* a, const uint32_t* b) {
    asm volatile(
        "mma.sync.aligned.m16n8k16.row.col.f32.bf16.bf16.f32 "
        "{%0,%1,%2,%3}, {%4,%5,%6,%7}, {%8,%9}, {%0,%1,%2,%3};"
        : "+f"(d[0]), "+f"(d[1]), "+f"(d[2]), "+f"(d[3])
        : "r"(a[0]), "r"(a[1]), "r"(a[2]), "r"(a[3]), "r"(b[0]), "r"(b[1]));
}

constexpr int APAD = 20;
constexpr int BPAD = 132;

template <int EPI, bool GATHER>
__global__ __launch_bounds__(256) void tgemm_kernel(
    const float* __restrict__ A, const float* __restrict__ B,
    const float* __restrict__ resid, float* __restrict__ C,
    int M, int K, int N,
    const int* __restrict__ elist, const int* __restrict__ ecount,
    const float* __restrict__ wslot, int ashift, size_t bExpertStride)
{
    __shared__ float As[2][128][APAD];
    __shared__ float Bs[2][16][BPAD];

    const int tid  = threadIdx.x;
    const int warp = tid >> 5;
    const int lane = tid & 31;
    const int wy = warp & 1;
    const int wx = warp >> 1;
    const int mW = wy * 64;
    const int nW = wx * 32;
    const int l4 = lane >> 2;
    const int lm = lane & 3;

    const int n0 = blockIdx.x * 128;

    int e = 0, cnt = 0, rt = 0, m0 = 0;
    const float* Bbase = B;
    if (GATHER) {
        e = blockIdx.z;
        cnt = ecount[e];
        rt = blockIdx.y * 128;
        if (rt >= cnt) return;
        Bbase = B + (size_t)e * bExpertStride;
    } else {
        m0 = blockIdx.y * 128;
    }

    const int arow  = tid >> 1;
    const int acolg = (tid & 1) * 8;
    const int brow  = tid >> 4;
    const int bcol  = (tid & 15) * 8;

    const float* aptr;
    int asz = 16;
    if (GATHER) {
        int g = rt + arow;
        bool valid = g < cnt;
        int slot = valid ? elist[e * NT + g] : 0;
        aptr = A + (size_t)(slot >> ashift) * K + acolg;
        asz = valid ? 16 : 0;
    } else {
        aptr = A + (size_t)(m0 + arow) * K + acolg;
    }
    const float* bptr = Bbase + n0 + bcol;

    uint32_t dA0 = (uint32_t)__cvta_generic_to_shared(&As[0][arow][acolg]);
    uint32_t dA1 = dA0 + 16;
    uint32_t dB0 = (uint32_t)__cvta_generic_to_shared(&Bs[0][brow][bcol]);
    uint32_t dB1 = dB0 + 16;
    const uint32_t bufStrideA = 128 * APAD * 4;
    const uint32_t bufStrideB = 16 * BPAD * 4;

    float acc[4][4][4];
    #pragma unroll
    for (int i = 0; i < 4; i++)
        #pragma unroll
        for (int j = 0; j < 4; j++)
            #pragma unroll
            for (int c = 0; c < 4; c++) acc[i][j][c] = 0.f;

    const int KT = K >> 4;

    cp16(dA0, aptr + 0, asz);
    cp16(dA1, aptr + 4, asz);
    cp16(dB0, bptr + (size_t)brow * N, 16);
    cp16(dB1, bptr + (size_t)brow * N + 4, 16);
    cp_commit();

    int buf = 0;
    for (int kt = 0; kt < KT; kt++) {
        if (kt + 1 < KT) {
            int k0 = (kt + 1) * 16;
            int nb = buf ^ 1;
            cp16(dA0 + nb * bufStrideA, aptr + k0,     asz);
            cp16(dA1 + nb * bufStrideA, aptr + k0 + 4, asz);
            cp16(dB0 + nb * bufStrideB, bptr + (size_t)(k0 + brow) * N,     16);
            cp16(dB1 + nb * bufStrideB, bptr + (size_t)(k0 + brow) * N + 4, 16);
            cp_commit();
            cp_wait<1>();
        } else {
            cp_wait<0>();
        }
        __syncthreads();

        uint32_t ahi[4][4], alo[4][4];
        #pragma unroll
        for (int mi = 0; mi < 4; mi++) {
            int r = mW + mi * 16 + l4;
            float2 p00 = *(const float2*)&As[buf][r    ][2 * lm];
            float2 p10 = *(const float2*)&As[buf][r + 8][2 * lm];
            float2 p01 = *(const float2*)&As[buf][r    ][2 * lm + 8];
            float2 p11 = *(const float2*)&As[buf][r + 8][2 * lm + 8];
            split2(p00.x, p00.y, ahi[mi][0], alo[mi][0]);
            split2(p10.x, p10.y, ahi[mi][1], alo[mi][1]);
            split2(p01.x, p01.y, ahi[mi][2], alo[mi][2]);
            split2(p11.x, p11.y, ahi[mi][3], alo[mi][3]);
        }
        #pragma unroll
        for (int ni = 0; ni < 4; ni++) {
            int c = nW + ni * 8 + l4;
            float b00 = Bs[buf][2 * lm    ][c];
            float b01 = Bs[buf][2 * lm + 1][c];
            float b08 = Bs[buf][2 * lm + 8][c];
            float b09 = Bs[buf][2 * lm + 9][c];
            uint32_t bhi[2], blo[2];
            split2(b00, b01, bhi[0], blo[0]);
            split2(b08, b09, bhi[1], blo[1]);
            #pragma unroll
            for (int mi = 0; mi < 4; mi++) {
                mma_bf16(acc[mi][ni], ahi[mi], bhi);
                mma_bf16(acc[mi][ni], ahi[mi], blo);
                mma_bf16(acc[mi][ni], alo[mi], bhi);
            }
        }
        __syncthreads();
        buf ^= 1;
    }

    #pragma unroll
    for (int mi = 0; mi < 4; mi++) {
        int r0 = mW + mi * 16 + l4;
        int r1 = r0 + 8;
        size_t crow0, crow1;
        bool v0 = true, v1 = true;
        float w0 = 1.f, w1 = 1.f;
        if (GATHER) {
            int g0 = rt + r0, g1 = rt + r1;
            v0 = g0 < cnt; v1 = g1 < cnt;
            int s0 = v0 ? elist[e * NT + g0] : 0;
            int s1 = v1 ? elist[e * NT + g1] : 0;
            crow0 = (size_t)s0 * N;
            crow1 = (size_t)s1 * N;
            if (EPI == 3) { w0 = v0 ? wslot[s0] : 0.f; w1 = v1 ? wslot[s1] : 0.f; }
        } else {
            crow0 = (size_t)(m0 + r0) * N;
            crow1 = (size_t)(m0 + r1) * N;
        }
        #pragma unroll
        for (int ni = 0; ni < 4; ni++) {
            int col = n0 + nW + ni * 8 + 2 * lm;
            float x0 = acc[mi][ni][0], x1 = acc[mi][ni][1];
            float x2 = acc[mi][ni][2], x3 = acc[mi][ni][3];
            if (EPI == 1) {
                const float* rp0 = resid + crow0 + col;
                const float* rp1 = resid + crow1 + col;
                x0 += rp0[0]; x1 += rp0[1];
                x2 += rp1[0]; x3 += rp1[1];
            } else if (EPI == 2) {
                x0 = x0 / (1.f + __expf(-x0));
                x1 = x1 / (1.f + __expf(-x1));
                x2 = x2 / (1.f + __expf(-x2));
                x3 = x3 / (1.f + __expf(-x3));
            } else if (EPI == 3) {
                x0 *= w0; x1 *= w0; x2 *= w1; x3 *= w1;
            }
            if (v0) *(float2*)&C[crow0 + col] = make_float2(x0, x1);
            if (v1) *(float2*)&C[crow1 + col] = make_float2(x2, x3);
        }
    }
}

__global__ __launch_bounds__(256) void rope_kernel(
    float* __restrict__ q, float* __restrict__ k, const float* __restrict__ freqs)
{
    int p = blockIdx.x * 256 + threadIdx.x;
    int t = p >> 9;
    int r = p & 511;
    int hh = r >> 6;
    int i  = r & 63;
    int s  = t & (Sc - 1);
    float f = freqs[s * 64 + i];
    float c = cosf(f), sn = sinf(f);
    size_t base = (size_t)t * Dc + hh * HDc + 2 * i;
    float e = q[base], o = q[base + 1];
    q[base] = e * c - o * sn; q[base + 1] = e * sn + o * c;
    e = k[base]; o = k[base + 1];
    k[base] = e * c - o * sn; k[base + 1] = e * sn + o * c;
}

// ---------------------------------------------------------------------------
// Tensor-core flash attention: 64 q x 64 k tiles, HD=128, bf16 3-MMA split.
// 8 warps: wy = warp>>1 (4 in M, 16 rows each), wx = warp&1 (2 in N).
// ---------------------------------------------------------------------------
constexpr int QPAD = 136;  // Q/K/V smem row stride (floats)
constexpr int PPAD = 72;   // P smem row stride
constexpr int FL_Q  = 0;
constexpr int FL_K  = FL_Q + 64 * QPAD;
constexpr int FL_V  = FL_K + 64 * QPAD;
constexpr int FL_P  = FL_V + 64 * QPAD;
constexpr int FL_RM = FL_P + 64 * PPAD;       // rowmax [64][2]
constexpr int FL_RS = FL_RM + 64 * 2;         // rowsum [64][2]
constexpr int FLASH_SMEM = (FL_RS + 64 * 2) * 4;

__global__ __launch_bounds__(256) void flash_tc_kernel(
    const float* __restrict__ q, const float* __restrict__ k,
    const float* __restrict__ v, float* __restrict__ ao)
{
    extern __shared__ float sm[];
    float* Qs = sm + FL_Q;
    float* Ks = sm + FL_K;
    float* Vs = sm + FL_V;
    float* Ps = sm + FL_P;
    float* RM = sm + FL_RM;
    float* RS = sm + FL_RS;

    const int tid  = threadIdx.x;
    const int warp = tid >> 5;
    const int lane = tid & 31;
    const int wy = warp >> 1;      // 0..3 (M)
    const int wx = warp & 1;       // 0..1 (N)
    const int g  = lane >> 2;      // 0..7
    const int lm = lane & 3;       // 0..3

    const int qb = blockIdx.x, hh = blockIdx.y, b = blockIdx.z;
    const size_t qbase = ((size_t)(b * Sc + qb * 64)) * Dc + hh * HDc;
    const float scale = 0.08838834764831845f;   // 1/sqrt(128)

    // rows this thread owns (within the 64-row q tile)
    const int row0 = wy * 16 + g;
    const int row1 = row0 + 8;

    // load Q tile (scaled), stride QPAD
    #pragma unroll
    for (int i = 0; i < 8; i++) {
        int li = tid + i * 256;
        int r = li >> 5, c = (li & 31) * 4;
        float4 val = *(const float4*)(q + qbase + (size_t)r * Dc + c);
        Qs[r * QPAD + c + 0] = val.x * scale;
        Qs[r * QPAD + c + 1] = val.y * scale;
        Qs[r * QPAD + c + 2] = val.z * scale;
        Qs[r * QPAD + c + 3] = val.w * scale;
    }

    float oacc[8][4];
    #pragma unroll
    for (int ni = 0; ni < 8; ni++)
        #pragma unroll
        for (int c = 0; c < 4; c++) oacc[ni][c] = 0.f;
    float m0s = -1e30f, m1s = -1e30f, l0s = 0.f, l1s = 0.f;

    for (int kb = 0; kb <= qb; kb++) {
        const size_t kbase = ((size_t)(b * Sc + kb * 64)) * Dc + hh * HDc;
        #pragma unroll
        for (int i = 0; i < 8; i++) {
            int li = tid + i * 256;
            int r = li >> 5, c = (li & 31) * 4;
            float4 kv = *(const float4*)(k + kbase + (size_t)r * Dc + c);
            float4 vv = *(const float4*)(v + kbase + (size_t)r * Dc + c);
            Ks[r * QPAD + c + 0] = kv.x; Ks[r * QPAD + c + 1] = kv.y;
            Ks[r * QPAD + c + 2] = kv.z; Ks[r * QPAD + c + 3] = kv.w;
            Vs[r * QPAD + c + 0] = vv.x; Vs[r * QPAD + c + 1] = vv.y;
            Vs[r * QPAD + c + 2] = vv.z; Vs[r * QPAD + c + 3] = vv.w;
        }
        __syncthreads();

        // ---- S = Q @ K^T : warp tile 16(M) x 32(N), k over 128 ----
        float sacc[4][4];
        #pragma unroll
        for (int ni = 0; ni < 4; ni++)
            #pragma unroll
            for (int c = 0; c < 4; c++) sacc[ni][c] = 0.f;

        #pragma unroll
        for (int ks = 0; ks < 8; ks++) {
            int k0 = ks * 16;
            uint32_t ahi[4], alo[4];
            {
                float2 p00 = *(const float2*)&Qs[row0 * QPAD + k0 + 2 * lm];
                float2 p10 = *(const float2*)&Qs[row1 * QPAD + k0 + 2 * lm];
                float2 p01 = *(const float2*)&Qs[row0 * QPAD + k0 + 2 * lm + 8];
                float2 p11 = *(const float2*)&Qs[row1 * QPAD + k0 + 2 * lm + 8];
                split2(p00.x, p00.y, ahi[0], alo[0]);
                split2(p10.x, p10.y, ahi[1], alo[1]);
                split2(p01.x, p01.y, ahi[2], alo[2]);
                split2(p11.x, p11.y, ahi[3], alo[3]);
            }
            #pragma unroll
            for (int ni = 0; ni < 4; ni++) {
                int ck = wx * 32 + ni * 8 + g;     // key index (S column)
                float b0 = Ks[ck * QPAD + k0 + 2 * lm];
                float b1 = Ks[ck * QPAD + k0 + 2 * lm + 1];
                float b2 = Ks[ck * QPAD + k0 + 2 * lm + 8];
                float b3 = Ks[ck * QPAD + k0 + 2 * lm + 9];
                uint32_t bhi[2], blo[2];
                split2(b0, b1, bhi[0], blo[0]);
                split2(b2, b3, bhi[1], blo[1]);
                mma_bf16(sacc[ni], ahi, bhi);
                mma_bf16(sacc[ni], ahi, blo);
                mma_bf16(sacc[ni], alo, bhi);
            }
        }

        // ---- causal mask ----
        if (kb == qb) {
            int qa0 = qb * 64 + row0;
            int qa1 = qb * 64 + row1;
            #pragma unroll
            for (int ni = 0; ni < 4; ni++) {
                int ka = kb * 64 + wx * 32 + ni * 8 + 2 * lm;
                if (ka     > qa0) sacc[ni][0] = -1e30f;
                if (ka + 1 > qa0) sacc[ni][1] = -1e30f;
                if (ka     > qa1) sacc[ni][2] = -1e30f;
                if (ka + 1 > qa1) sacc[ni][3] = -1e30f;
            }
        }

        // ---- warp-local row max over this warp's 32 cols ----
        float rm0 = -1e30f, rm1 = -1e30f;
        #pragma unroll
        for (int ni = 0; ni < 4; ni++) {
            rm0 = fmaxf(rm0, fmaxf(sacc[ni][0], sacc[ni][1]));
            rm1 = fmaxf(rm1, fmaxf(sacc[ni][2], sacc[ni][3]));
        }
        rm0 = fmaxf(rm0, __shfl_xor_sync(0xffffffffu, rm0, 1));
        rm0 = fmaxf(rm0, __shfl_xor_sync(0xffffffffu, rm0, 2));
        rm1 = fmaxf(rm1, __shfl_xor_sync(0xffffffffu, rm1, 1));
        rm1 = fmaxf(rm1, __shfl_xor_sync(0xffffffffu, rm1, 2));
        if (lm == 0) {
            RM[row0 * 2 + wx] = rm0;
            RM[row1 * 2 + wx] = rm1;
        }
        __syncthreads();

        float mn0 = fmaxf(m0s, fmaxf(RM[row0 * 2], RM[row0 * 2 + 1]));
        float mn1 = fmaxf(m1s, fmaxf(RM[row1 * 2], RM[row1 * 2 + 1]));

        // ---- p = exp(s - mn), partial row sums, store P ----
        float ps0 = 0.f, ps1 = 0.f;
        #pragma unroll
        for (int ni = 0; ni < 4; ni++) {
            float p0 = __expf(sacc[ni][0] - mn0);
            float p1 = __expf(sacc[ni][1] - mn0);
            float p2 = __expf(sacc[ni][2] - mn1);
            float p3 = __expf(sacc[ni][3] - mn1);
            ps0 += p0 + p1; ps1 += p2 + p3;
            int pc = wx * 32 + ni * 8 + 2 * lm;
            *(float2*)&Ps[row0 * PPAD + pc] = make_float2(p0, p1);
            *(float2*)&Ps[row1 * PPAD + pc] = make_float2(p2, p3);
        }
        ps0 += __shfl_xor_sync(0xffffffffu, ps0, 1);
        ps0 += __shfl_xor_sync(0xffffffffu, ps0, 2);
        ps1 += __shfl_xor_sync(0xffffffffu, ps1, 1);
        ps1 += __shfl_xor_sync(0xffffffffu, ps1, 2);
        if (lm == 0) {
            RS[row0 * 2 + wx] = ps0;
            RS[row1 * 2 + wx] = ps1;
        }
        __syncthreads();

        float sc0 = __expf(m0s - mn0);
        float sc1 = __expf(m1s - mn1);
        l0s = l0s * sc0 + RS[row0 * 2] + RS[row0 * 2 + 1];
        l1s = l1s * sc1 + RS[row1 * 2] + RS[row1 * 2 + 1];
        m0s = mn0; m1s = mn1;
        #pragma unroll
        for (int ni = 0; ni < 8; ni++) {
            oacc[ni][0] *= sc0; oacc[ni][1] *= sc0;
            oacc[ni][2] *= sc1; oacc[ni][3] *= sc1;
        }

        // ---- O += P @ V : warp tile 16(M) x 64(N), k over 64 keys ----
        #pragma unroll
        for (int ks = 0; ks < 4; ks++) {
            int k0 = ks * 16;
            uint32_t ahi[4], alo[4];
            {
                float2 p00 = *(const float2*)&Ps[row0 * PPAD + k0 + 2 * lm];
                float2 p10 = *(const float2*)&Ps[row1 * PPAD + k0 + 2 * lm];
                float2 p01 = *(const float2*)&Ps[row0 * PPAD + k0 + 2 * lm + 8];
                float2 p11 = *(const float2*)&Ps[row1 * PPAD + k0 + 2 * lm + 8];
                split2(p00.x, p00.y, ahi[0], alo[0]);
                split2(p10.x, p10.y, ahi[1], alo[1]);
                split2(p01.x, p01.y, ahi[2], alo[2]);
                split2(p11.x, p11.y, ahi[3], alo[3]);
            }
            #pragma unroll
            for (int ni = 0; ni < 8; ni++) {
                int vc = wx * 64 + ni * 8 + g;     // headdim column
                float b0 = Vs[(k0 + 2 * lm)     * QPAD + vc];
                float b1 = Vs[(k0 + 2 * lm + 1) * QPAD + vc];
                float b2 = Vs[(k0 + 2 * lm + 8) * QPAD + vc];
                float b3 = Vs[(k0 + 2 * lm + 9) * QPAD + vc];
                uint32_t bhi[2], blo[2];
                split2(b0, b1, bhi[0], blo[0]);
                split2(b2, b3, bhi[1], blo[1]);
                mma_bf16(oacc[ni], ahi, bhi);
                mma_bf16(oacc[ni], ahi, blo);
                mma_bf16(oacc[ni], alo, bhi);
            }
        }
        __syncthreads();
    }

    // ---- write O / l ----
    float inv0 = 1.f / l0s;
    float inv1 = 1.f / l1s;
    #pragma unroll
    for (int ni = 0; ni < 8; ni++) {
        int col = wx * 64 + ni * 8 + 2 * lm;
        *(float2*)&ao[qbase + (size_t)row0 * Dc + col] =
            make_float2(oacc[ni][0] * inv0, oacc[ni][1] * inv0);
        *(float2*)&ao[qbase + (size_t)row1 * Dc + col] =
            make_float2(oacc[ni][2] * inv1, oacc[ni][3] * inv1);
    }
}

__global__ __launch_bounds__(256) void gate_kernel(
    const float* __restrict__ hn, const float* __restrict__ Wg,
    float* __restrict__ wslot, int* __restrict__ elist, int* __restrict__ ecount)
{
    int gtid = blockIdx.x * 256 + threadIdx.x;
    int t = gtid >> 5;
    int lane = gtid & 31;
    if (t >= NT) return;

    float acc[Ec];
    #pragma unroll
    for (int e = 0; e < Ec; e++) acc[e] = 0.f;
    const float* xr = hn + (size_t)t * Dc;
    for (int d = lane; d < Dc; d += 32) {
        float xv = xr[d];
        const float* wr = Wg + (size_t)d * Ec;
        #pragma unroll
        for (int e = 0; e < Ec; e++) acc[e] = fmaf(xv, wr[e], acc[e]);
    }
    #pragma unroll
    for (int e = 0; e < Ec; e++)
        #pragma unroll
        for (int m = 16; m >= 1; m >>= 1)
            acc[e] += __shfl_xor_sync(0xffffffffu, acc[e], m);

    if (lane == 0) {
        int e0 = 0; float l0 = acc[0];
        #pragma unroll
        for (int e = 1; e < Ec; e++) if (acc[e] > l0) { l0 = acc[e]; e0 = e; }
        int e1 = -1; float l1 = -3.4e38f;
        #pragma unroll
        for (int e = 0; e < Ec; e++) {
            if (e == e0) continue;
            if (acc[e] > l1) { l1 = acc[e]; e1 = e; }
        }
        float t1 = expf(l1 - l0);
        float w0 = 1.f / (1.f + t1);
        float w1 = t1 / (1.f + t1);
        wslot[2 * t]     = w0;
        wslot[2 * t + 1] = w1;
        int p0 = atomicAdd(&ecount[e0], 1);
        elist[e0 * NT + p0] = 2 * t;
        int p1 = atomicAdd(&ecount[e1], 1);
        elist[e1 * NT + p1] = 2 * t + 1;
    }
}

__global__ __launch_bounds__(256) void combine_kernel(
    const float* __restrict__ h, const float* __restrict__ moeout,
    float* __restrict__ out)
{
    size_t i = (size_t)blockIdx.x * 256 + threadIdx.x;
    size_t t = i >> 10, d = i & 1023;
    out[i] = h[i] + moeout[(2 * t) * (size_t)Dc + d]
                  + moeout[(2 * t + 1) * (size_t)Dc + d];
}

extern "C" void kernel_launch(void* const* d_in, const int* in_sizes, int n_in,
                              void* d_out, int out_size)
{
    const float* x     = (const float*)d_in[0];
    const float* freqs = (const float*)d_in[1];
    const float* g1    = (const float*)d_in[2];
    const float* b1    = (const float*)d_in[3];
    const float* g2    = (const float*)d_in[4];
    const float* b2    = (const float*)d_in[5];
    const float* Wq    = (const float*)d_in[6];
    const float* Wdkv  = (const float*)d_in[7];
    const float* Wuk   = (const float*)d_in[8];
    const float* Wuv   = (const float*)d_in[9];
    const float* Wo    = (const float*)d_in[10];
    const float* Wg    = (const float*)d_in[11];
    const float* W1    = (const float*)d_in[12];
    const float* W2    = (const float*)d_in[13];
    float* out = (float*)d_out;

    void* bufp = nullptr;
    cudaGetSymbolAddress(&bufp, g_buf);
    float* buf   = (float*)bufp;
    float* xn    = buf + OFF_XN;
    float* qb_   = buf + OFF_Q;
    float* kb_   = buf + OFF_K;
    float* vb_   = buf + OFF_V;
    float* lat   = buf + OFF_LAT;
    float* ao    = buf + OFF_AO;
    float* h     = buf + OFF_H;
    float* hn    = buf + OFF_HN;
    float* act   = buf + OFF_ACT;
    float* moeo  = buf + OFF_MOE;
    float* wslot = buf + OFF_WSLOT;
    int*   elist = (int*)(buf + OFF_ELIST);
    int*   ecnt  = (int*)(buf + OFF_ECNT);

    cudaFuncSetAttribute(flash_tc_kernel,
                         cudaFuncAttributeMaxDynamicSharedMemorySize, FLASH_SMEM);

    reset_kernel<<<1, 32>>>(ecnt);
    ln_kernel<<<NT, 256>>>(x, g1, b1, xn);

    tgemm_kernel<0, false><<<dim3(Dc / 128, NT / 128), 256>>>(
        xn, Wq, nullptr, qb_, NT, Dc, Dc, nullptr, nullptr, nullptr, 0, 0);
    tgemm_kernel<0, false><<<dim3(Lc / 128, NT / 128), 256>>>(
        xn, Wdkv, nullptr, lat, NT, Dc, Lc, nullptr, nullptr, nullptr, 0, 0);
    tgemm_kernel<0, false><<<dim3(Dc / 128, NT / 128), 256>>>(
        lat, Wuk, nullptr, kb_, NT, Lc, Dc, nullptr, nullptr, nullptr, 0, 0);
    tgemm_kernel<0, false><<<dim3(Dc / 128, NT / 128), 256>>>(
        lat, Wuv, nullptr, vb_, NT, Lc, Dc, nullptr, nullptr, nullptr, 0, 0);

    rope_kernel<<<(NT * (Dc / 2)) / 256, 256>>>(qb_, kb_, freqs);

    flash_tc_kernel<<<dim3(Sc / 64, Hc, Bc), 256, FLASH_SMEM>>>(qb_, kb_, vb_, ao);

    tgemm_kernel<1, false><<<dim3(Dc / 128, NT / 128), 256>>>(
        ao, Wo, x, h, NT, Dc, Dc, nullptr, nullptr, nullptr, 0, 0);

    ln_kernel<<<NT, 256>>>(h, g2, b2, hn);

    gate_kernel<<<(NT * 32) / 256, 256>>>(hn, Wg, wslot, elist, ecnt);

    tgemm_kernel<2, true><<<dim3(Fc / 128, NT / 128, Ec), 256>>>(
        hn, W1, nullptr, act, 0, Dc, Fc, elist, ecnt, nullptr, 1, (size_t)Dc * Fc);
    tgemm_kernel<3, true><<<dim3(Dc / 128, NT / 128, Ec), 256>>>(
        act, W2, nullptr, moeo, 0, Fc, Dc, elist, ecnt, wslot, 0, (size_t)Fc * Dc);

    combine_kernel<<<(NT * Dc) / 256, 256>>>(h, moeo, out);
}

// round 8
// speedup vs baseline: 2.5834x; 1.0330x over previous
#include <cuda_runtime.h>
#include <cuda_bf16.h>
#include <math.h>
#include <stdint.h>

constexpr int Bc  = 2;
constexpr int Sc  = 2048;
constexpr int Dc  = 1024;
constexpr int Lc  = 512;
constexpr int Hc  = 8;
constexpr int HDc = 128;
constexpr int Ec  = 8;
constexpr int Fc  = 4096;
constexpr int NT  = Bc * Sc;

constexpr size_t OFF_XN    = 0;
constexpr size_t OFF_Q     = OFF_XN    + (size_t)NT * Dc;
constexpr size_t OFF_K     = OFF_Q     + (size_t)NT * Dc;
constexpr size_t OFF_V     = OFF_K     + (size_t)NT * Dc;
constexpr size_t OFF_LAT   = OFF_V     + (size_t)NT * Dc;
constexpr size_t OFF_AO    = OFF_LAT   + (size_t)NT * Lc;
constexpr size_t OFF_H     = OFF_AO    + (size_t)NT * Dc;
constexpr size_t OFF_HN    = OFF_H     + (size_t)NT * Dc;
constexpr size_t OFF_ACT   = OFF_HN    + (size_t)NT * Dc;
constexpr size_t OFF_MOE   = OFF_ACT   + (size_t)2 * NT * Fc;
constexpr size_t OFF_WSLOT = OFF_MOE   + (size_t)2 * NT * Dc;
constexpr size_t OFF_ELIST = OFF_WSLOT + (size_t)2 * NT;
constexpr size_t OFF_ECNT  = OFF_ELIST + (size_t)Ec * NT;
constexpr size_t BUF_TOTAL = OFF_ECNT + 64;

__device__ float g_buf[BUF_TOTAL];

__global__ void reset_kernel(int* ecount) {
    if (threadIdx.x < Ec) ecount[threadIdx.x] = 0;
}

__global__ __launch_bounds__(256) void ln_kernel(
    const float* __restrict__ x, const float* __restrict__ g,
    const float* __restrict__ b, float* __restrict__ y)
{
    int t = blockIdx.x;
    int tid = threadIdx.x;
    const float* xr = x + (size_t)t * Dc;
    float s = 0.f, s2 = 0.f;
    #pragma unroll
    for (int i = tid; i < Dc; i += 256) { float v = xr[i]; s += v; s2 += v * v; }
    __shared__ float sh[2][256];
    sh[0][tid] = s; sh[1][tid] = s2;
    __syncthreads();
    for (int st = 128; st > 0; st >>= 1) {
        if (tid < st) { sh[0][tid] += sh[0][tid + st]; sh[1][tid] += sh[1][tid + st]; }
        __syncthreads();
    }
    float mu   = sh[0][0] * (1.f / Dc);
    float var  = sh[1][0] * (1.f / Dc) - mu * mu;
    float rstd = rsqrtf(var + 1e-5f);
    float* yr = y + (size_t)t * Dc;
    #pragma unroll
    for (int i = tid; i < Dc; i += 256)
        yr[i] = (xr[i] - mu) * rstd * g[i] + b[i];
}

// split a pair of fp32 into bf16x2 hi + bf16x2 lo  (first arg in low half)
__device__ __forceinline__ void split2(float x0, float x1, uint32_t& hi, uint32_t& lo) {
    uint32_t h;
    asm("cvt.rn.bf16x2.f32 %0, %1, %2;" : "=r"(h) : "f"(x1), "f"(x0));
    float h0 = __uint_as_float(h << 16);
    float h1 = __uint_as_float(h & 0xffff0000u);
    uint32_t l;
    asm("cvt.rn.bf16x2.f32 %0, %1, %2;" : "=r"(l) : "f"(x1 - h1), "f"(x0 - h0));
    hi = h; lo = l;
}

__device__ __forceinline__ void mma_bf16(float* d, const uint32_t* a, const uint32_t* b) {
    asm volatile(
        "mma.sync.aligned.m16n8k16.row.col.f32.bf16.bf16.f32 "
        "{%0,%1,%2,%3}, {%4,%5,%6,%7}, {%8,%9}, {%0,%1,%2,%3};"
        : "+f"(d[0]), "+f"(d[1]), "+f"(d[2]), "+f"(d[3])
        : "r"(a[0]), "r"(a[1]), "r"(a[2]), "r"(a[3]), "r"(b[0]), "r"(b[1]));
}

// ---------------------------------------------------------------------------
// tgemm v2: pre-split bf16x2 smem tiles. 128x128 block tile, BK=16.
// A smem: Ahi/Alo[m][kpair] (12-word row stride, conflict-free frag reads)
// B smem: Bhi/Blo[kpair][n] (136-word row stride, conflict-free frag reads)
// 8 warps: 2(M) x 4(N); warp tile 64x32; register-staged global prefetch.
// EPI: 0 none, 1 +resid, 2 silu, 3 *wslot.  GATHER: rows via elist.
// ---------------------------------------------------------------------------
constexpr int PA = 12;    // A smem row stride in u32 (8 used)
constexpr int PB = 136;   // B smem row stride in u32 (128 used)

template <int EPI, bool GATHER>
__global__ __launch_bounds__(256, 2) void tgemm_kernel(
    const float* __restrict__ A, const float* __restrict__ B,
    const float* __restrict__ resid, float* __restrict__ C,
    int M, int K, int N,
    const int* __restrict__ elist, const int* __restrict__ ecount,
    const float* __restrict__ wslot, int ashift, size_t bExpertStride)
{
    __shared__ uint32_t Ahi[128][PA], Alo[128][PA];
    __shared__ uint32_t Bhi[8][PB],   Blo[8][PB];

    const int tid  = threadIdx.x;
    const int warp = tid >> 5;
    const int lane = tid & 31;
    const int wy = warp & 1;
    const int wx = warp >> 1;
    const int mW = wy * 64;
    const int nW = wx * 32;
    const int g  = lane >> 2;     // groupID 0..7
    const int lm = lane & 3;      // thread-in-group 0..3

    const int n0 = blockIdx.x * 128;

    int e = 0, cnt = 0, rt = 0, m0 = 0;
    const float* Bbase = B;
    if (GATHER) {
        e = blockIdx.z;
        cnt = ecount[e];
        rt = blockIdx.y * 128;
        if (rt >= cnt) return;
        Bbase = B + (size_t)e * bExpertStride;
    } else {
        m0 = blockIdx.y * 128;
    }

    // A loader: thread -> row (tid>>1), k-half ((tid&1)*8)
    const int arow  = tid >> 1;
    const int acolg = (tid & 1) * 8;
    const int akp0  = (tid & 1) * 4;
    // B loader: thread -> kpair (tid>>5), n-group ((tid&31)*4)
    const int bkp   = tid >> 5;
    const int bn    = (tid & 31) * 4;

    const float* aptr;
    bool avalid = true;
    if (GATHER) {
        int gr = rt + arow;
        avalid = gr < cnt;
        int slot = avalid ? elist[e * NT + gr] : 0;
        aptr = A + (size_t)(slot >> ashift) * K + acolg;
    } else {
        aptr = A + (size_t)(m0 + arow) * K + acolg;
    }
    const float* bptr = Bbase + n0 + bn;

    float acc[4][4][4];
    #pragma unroll
    for (int i = 0; i < 4; i++)
        #pragma unroll
        for (int j = 0; j < 4; j++)
            #pragma unroll
            for (int c = 0; c < 4; c++) acc[i][j][c] = 0.f;

    const int KT = K >> 4;
    const float4 fz = make_float4(0.f, 0.f, 0.f, 0.f);

    // stage tile 0
    float4 a0 = avalid ? *(const float4*)(aptr)     : fz;
    float4 a1 = avalid ? *(const float4*)(aptr + 4) : fz;
    float4 b0v = *(const float4*)(bptr + (size_t)(2 * bkp) * N);
    float4 b1v = *(const float4*)(bptr + (size_t)(2 * bkp + 1) * N);

    for (int kt = 0; kt < KT; kt++) {
        if (kt > 0) __syncthreads();
        // store staged tile into smem with split
        {
            uint32_t h, l;
            uint4 vh, vl;
            split2(a0.x, a0.y, h, l); vh.x = h; vl.x = l;
            split2(a0.z, a0.w, h, l); vh.y = h; vl.y = l;
            split2(a1.x, a1.y, h, l); vh.z = h; vl.z = l;
            split2(a1.z, a1.w, h, l); vh.w = h; vl.w = l;
            *(uint4*)&Ahi[arow][akp0] = vh;
            *(uint4*)&Alo[arow][akp0] = vl;
            split2(b0v.x, b1v.x, h, l); vh.x = h; vl.x = l;
            split2(b0v.y, b1v.y, h, l); vh.y = h; vl.y = l;
            split2(b0v.z, b1v.z, h, l); vh.z = h; vl.z = l;
            split2(b0v.w, b1v.w, h, l); vh.w = h; vl.w = l;
            *(uint4*)&Bhi[bkp][bn] = vh;
            *(uint4*)&Blo[bkp][bn] = vl;
        }
        __syncthreads();

        // prefetch next tile into registers (overlaps with compute)
        if (kt + 1 < KT) {
            int k0 = (kt + 1) * 16;
            a0 = avalid ? *(const float4*)(aptr + k0)     : fz;
            a1 = avalid ? *(const float4*)(aptr + k0 + 4) : fz;
            b0v = *(const float4*)(bptr + (size_t)(k0 + 2 * bkp) * N);
            b1v = *(const float4*)(bptr + (size_t)(k0 + 2 * bkp + 1) * N);
        }

        // A fragments (pure LDS.32, no conversion)
        uint32_t ahi[4][4], alo[4][4];
        #pragma unroll
        for (int mi = 0; mi < 4; mi++) {
            int r = mW + mi * 16 + g;
            ahi[mi][0] = Ahi[r    ][lm];
            ahi[mi][1] = Ahi[r + 8][lm];
            ahi[mi][2] = Ahi[r    ][lm + 4];
            ahi[mi][3] = Ahi[r + 8][lm + 4];
            alo[mi][0] = Alo[r    ][lm];
            alo[mi][1] = Alo[r + 8][lm];
            alo[mi][2] = Alo[r    ][lm + 4];
            alo[mi][3] = Alo[r + 8][lm + 4];
        }
        #pragma unroll
        for (int ni = 0; ni < 4; ni++) {
            int c = nW + ni * 8 + g;
            uint32_t bhi[2], blo[2];
            bhi[0] = Bhi[lm    ][c];
            bhi[1] = Bhi[lm + 4][c];
            blo[0] = Blo[lm    ][c];
            blo[1] = Blo[lm + 4][c];
            #pragma unroll
            for (int mi = 0; mi < 4; mi++) {
                mma_bf16(acc[mi][ni], ahi[mi], bhi);
                mma_bf16(acc[mi][ni], ahi[mi], blo);
                mma_bf16(acc[mi][ni], alo[mi], bhi);
            }
        }
    }

    #pragma unroll
    for (int mi = 0; mi < 4; mi++) {
        int r0 = mW + mi * 16 + g;
        int r1 = r0 + 8;
        size_t crow0, crow1;
        bool v0 = true, v1 = true;
        float w0 = 1.f, w1 = 1.f;
        if (GATHER) {
            int g0 = rt + r0, g1 = rt + r1;
            v0 = g0 < cnt; v1 = g1 < cnt;
            int s0 = v0 ? elist[e * NT + g0] : 0;
            int s1 = v1 ? elist[e * NT + g1] : 0;
            crow0 = (size_t)s0 * N;
            crow1 = (size_t)s1 * N;
            if (EPI == 3) { w0 = v0 ? wslot[s0] : 0.f; w1 = v1 ? wslot[s1] : 0.f; }
        } else {
            crow0 = (size_t)(m0 + r0) * N;
            crow1 = (size_t)(m0 + r1) * N;
        }
        #pragma unroll
        for (int ni = 0; ni < 4; ni++) {
            int col = n0 + nW + ni * 8 + 2 * lm;
            float x0 = acc[mi][ni][0], x1 = acc[mi][ni][1];
            float x2 = acc[mi][ni][2], x3 = acc[mi][ni][3];
            if (EPI == 1) {
                const float* rp0 = resid + crow0 + col;
                const float* rp1 = resid + crow1 + col;
                x0 += rp0[0]; x1 += rp0[1];
                x2 += rp1[0]; x3 += rp1[1];
            } else if (EPI == 2) {
                x0 = x0 / (1.f + __expf(-x0));
                x1 = x1 / (1.f + __expf(-x1));
                x2 = x2 / (1.f + __expf(-x2));
                x3 = x3 / (1.f + __expf(-x3));
            } else if (EPI == 3) {
                x0 *= w0; x1 *= w0; x2 *= w1; x3 *= w1;
            }
            if (v0) *(float2*)&C[crow0 + col] = make_float2(x0, x1);
            if (v1) *(float2*)&C[crow1 + col] = make_float2(x2, x3);
        }
    }
}

__global__ __launch_bounds__(256) void rope_kernel(
    float* __restrict__ q, float* __restrict__ k, const float* __restrict__ freqs)
{
    int p = blockIdx.x * 256 + threadIdx.x;
    int t = p >> 9;
    int r = p & 511;
    int hh = r >> 6;
    int i  = r & 63;
    int s  = t & (Sc - 1);
    float f = freqs[s * 64 + i];
    float c = cosf(f), sn = sinf(f);
    size_t base = (size_t)t * Dc + hh * HDc + 2 * i;
    float e = q[base], o = q[base + 1];
    q[base] = e * c - o * sn; q[base + 1] = e * sn + o * c;
    e = k[base]; o = k[base + 1];
    k[base] = e * c - o * sn; k[base + 1] = e * sn + o * c;
}

// ---------------------------------------------------------------------------
// Tensor-core flash attention (unchanged from round 7)
// ---------------------------------------------------------------------------
constexpr int QPAD = 136;
constexpr int PPAD = 72;
constexpr int FL_Q  = 0;
constexpr int FL_K  = FL_Q + 64 * QPAD;
constexpr int FL_V  = FL_K + 64 * QPAD;
constexpr int FL_P  = FL_V + 64 * QPAD;
constexpr int FL_RM = FL_P + 64 * PPAD;
constexpr int FL_RS = FL_RM + 64 * 2;
constexpr int FLASH_SMEM = (FL_RS + 64 * 2) * 4;

__global__ __launch_bounds__(256) void flash_tc_kernel(
    const float* __restrict__ q, const float* __restrict__ k,
    const float* __restrict__ v, float* __restrict__ ao)
{
    extern __shared__ float sm[];
    float* Qs = sm + FL_Q;
    float* Ks = sm + FL_K;
    float* Vs = sm + FL_V;
    float* Ps = sm + FL_P;
    float* RM = sm + FL_RM;
    float* RS = sm + FL_RS;

    const int tid  = threadIdx.x;
    const int warp = tid >> 5;
    const int lane = tid & 31;
    const int wy = warp >> 1;
    const int wx = warp & 1;
    const int g  = lane >> 2;
    const int lm = lane & 3;

    const int qb = blockIdx.x, hh = blockIdx.y, b = blockIdx.z;
    const size_t qbase = ((size_t)(b * Sc + qb * 64)) * Dc + hh * HDc;
    const float scale = 0.08838834764831845f;

    const int row0 = wy * 16 + g;
    const int row1 = row0 + 8;

    #pragma unroll
    for (int i = 0; i < 8; i++) {
        int li = tid + i * 256;
        int r = li >> 5, c = (li & 31) * 4;
        float4 val = *(const float4*)(q + qbase + (size_t)r * Dc + c);
        Qs[r * QPAD + c + 0] = val.x * scale;
        Qs[r * QPAD + c + 1] = val.y * scale;
        Qs[r * QPAD + c + 2] = val.z * scale;
        Qs[r * QPAD + c + 3] = val.w * scale;
    }

    float oacc[8][4];
    #pragma unroll
    for (int ni = 0; ni < 8; ni++)
        #pragma unroll
        for (int c = 0; c < 4; c++) oacc[ni][c] = 0.f;
    float m0s = -1e30f, m1s = -1e30f, l0s = 0.f, l1s = 0.f;

    for (int kb = 0; kb <= qb; kb++) {
        const size_t kbase = ((size_t)(b * Sc + kb * 64)) * Dc + hh * HDc;
        #pragma unroll
        for (int i = 0; i < 8; i++) {
            int li = tid + i * 256;
            int r = li >> 5, c = (li & 31) * 4;
            float4 kv = *(const float4*)(k + kbase + (size_t)r * Dc + c);
            float4 vv = *(const float4*)(v + kbase + (size_t)r * Dc + c);
            Ks[r * QPAD + c + 0] = kv.x; Ks[r * QPAD + c + 1] = kv.y;
            Ks[r * QPAD + c + 2] = kv.z; Ks[r * QPAD + c + 3] = kv.w;
            Vs[r * QPAD + c + 0] = vv.x; Vs[r * QPAD + c + 1] = vv.y;
            Vs[r * QPAD + c + 2] = vv.z; Vs[r * QPAD + c + 3] = vv.w;
        }
        __syncthreads();

        float sacc[4][4];
        #pragma unroll
        for (int ni = 0; ni < 4; ni++)
            #pragma unroll
            for (int c = 0; c < 4; c++) sacc[ni][c] = 0.f;

        #pragma unroll
        for (int ks = 0; ks < 8; ks++) {
            int k0 = ks * 16;
            uint32_t ahi[4], alo[4];
            {
                float2 p00 = *(const float2*)&Qs[row0 * QPAD + k0 + 2 * lm];
                float2 p10 = *(const float2*)&Qs[row1 * QPAD + k0 + 2 * lm];
                float2 p01 = *(const float2*)&Qs[row0 * QPAD + k0 + 2 * lm + 8];
                float2 p11 = *(const float2*)&Qs[row1 * QPAD + k0 + 2 * lm + 8];
                split2(p00.x, p00.y, ahi[0], alo[0]);
                split2(p10.x, p10.y, ahi[1], alo[1]);
                split2(p01.x, p01.y, ahi[2], alo[2]);
                split2(p11.x, p11.y, ahi[3], alo[3]);
            }
            #pragma unroll
            for (int ni = 0; ni < 4; ni++) {
                int ck = wx * 32 + ni * 8 + g;
                float b0 = Ks[ck * QPAD + k0 + 2 * lm];
                float b1 = Ks[ck * QPAD + k0 + 2 * lm + 1];
                float b2 = Ks[ck * QPAD + k0 + 2 * lm + 8];
                float b3 = Ks[ck * QPAD + k0 + 2 * lm + 9];
                uint32_t bhi[2], blo[2];
                split2(b0, b1, bhi[0], blo[0]);
                split2(b2, b3, bhi[1], blo[1]);
                mma_bf16(sacc[ni], ahi, bhi);
                mma_bf16(sacc[ni], ahi, blo);
                mma_bf16(sacc[ni], alo, bhi);
            }
        }

        if (kb == qb) {
            int qa0 = qb * 64 + row0;
            int qa1 = qb * 64 + row1;
            #pragma unroll
            for (int ni = 0; ni < 4; ni++) {
                int ka = kb * 64 + wx * 32 + ni * 8 + 2 * lm;
                if (ka     > qa0) sacc[ni][0] = -1e30f;
                if (ka + 1 > qa0) sacc[ni][1] = -1e30f;
                if (ka     > qa1) sacc[ni][2] = -1e30f;
                if (ka + 1 > qa1) sacc[ni][3] = -1e30f;
            }
        }

        float rm0 = -1e30f, rm1 = -1e30f;
        #pragma unroll
        for (int ni = 0; ni < 4; ni++) {
            rm0 = fmaxf(rm0, fmaxf(sacc[ni][0], sacc[ni][1]));
            rm1 = fmaxf(rm1, fmaxf(sacc[ni][2], sacc[ni][3]));
        }
        rm0 = fmaxf(rm0, __shfl_xor_sync(0xffffffffu, rm0, 1));
        rm0 = fmaxf(rm0, __shfl_xor_sync(0xffffffffu, rm0, 2));
        rm1 = fmaxf(rm1, __shfl_xor_sync(0xffffffffu, rm1, 1));
        rm1 = fmaxf(rm1, __shfl_xor_sync(0xffffffffu, rm1, 2));
        if (lm == 0) {
            RM[row0 * 2 + wx] = rm0;
            RM[row1 * 2 + wx] = rm1;
        }
        __syncthreads();

        float mn0 = fmaxf(m0s, fmaxf(RM[row0 * 2], RM[row0 * 2 + 1]));
        float mn1 = fmaxf(m1s, fmaxf(RM[row1 * 2], RM[row1 * 2 + 1]));

        float ps0 = 0.f, ps1 = 0.f;
        #pragma unroll
        for (int ni = 0; ni < 4; ni++) {
            float p0 = __expf(sacc[ni][0] - mn0);
            float p1 = __expf(sacc[ni][1] - mn0);
            float p2 = __expf(sacc[ni][2] - mn1);
            float p3 = __expf(sacc[ni][3] - mn1);
            ps0 += p0 + p1; ps1 += p2 + p3;
            int pc = wx * 32 + ni * 8 + 2 * lm;
            *(float2*)&Ps[row0 * PPAD + pc] = make_float2(p0, p1);
            *(float2*)&Ps[row1 * PPAD + pc] = make_float2(p2, p3);
        }
        ps0 += __shfl_xor_sync(0xffffffffu, ps0, 1);
        ps0 += __shfl_xor_sync(0xffffffffu, ps0, 2);
        ps1 += __shfl_xor_sync(0xffffffffu, ps1, 1);
        ps1 += __shfl_xor_sync(0xffffffffu, ps1, 2);
        if (lm == 0) {
            RS[row0 * 2 + wx] = ps0;
            RS[row1 * 2 + wx] = ps1;
        }
        __syncthreads();

        float sc0 = __expf(m0s - mn0);
        float sc1 = __expf(m1s - mn1);
        l0s = l0s * sc0 + RS[row0 * 2] + RS[row0 * 2 + 1];
        l1s = l1s * sc1 + RS[row1 * 2] + RS[row1 * 2 + 1];
        m0s = mn0; m1s = mn1;
        #pragma unroll
        for (int ni = 0; ni < 8; ni++) {
            oacc[ni][0] *= sc0; oacc[ni][1] *= sc0;
            oacc[ni][2] *= sc1; oacc[ni][3] *= sc1;
        }

        #pragma unroll
        for (int ks = 0; ks < 4; ks++) {
            int k0 = ks * 16;
            uint32_t ahi[4], alo[4];
            {
                float2 p00 = *(const float2*)&Ps[row0 * PPAD + k0 + 2 * lm];
                float2 p10 = *(const float2*)&Ps[row1 * PPAD + k0 + 2 * lm];
                float2 p01 = *(const float2*)&Ps[row0 * PPAD + k0 + 2 * lm + 8];
                float2 p11 = *(const float2*)&Ps[row1 * PPAD + k0 + 2 * lm + 8];
                split2(p00.x, p00.y, ahi[0], alo[0]);
                split2(p10.x, p10.y, ahi[1], alo[1]);
                split2(p01.x, p01.y, ahi[2], alo[2]);
                split2(p11.x, p11.y, ahi[3], alo[3]);
            }
            #pragma unroll
            for (int ni = 0; ni < 8; ni++) {
                int vc = wx * 64 + ni * 8 + g;
                float b0 = Vs[(k0 + 2 * lm)     * QPAD + vc];
                float b1 = Vs[(k0 + 2 * lm + 1) * QPAD + vc];
                float b2 = Vs[(k0 + 2 * lm + 8) * QPAD + vc];
                float b3 = Vs[(k0 + 2 * lm + 9) * QPAD + vc];
                uint32_t bhi[2], blo[2];
                split2(b0, b1, bhi[0], blo[0]);
                split2(b2, b3, bhi[1], blo[1]);
                mma_bf16(oacc[ni], ahi, bhi);
                mma_bf16(oacc[ni], ahi, blo);
                mma_bf16(oacc[ni], alo, bhi);
            }
        }
        __syncthreads();
    }

    float inv0 = 1.f / l0s;
    float inv1 = 1.f / l1s;
    #pragma unroll
    for (int ni = 0; ni < 8; ni++) {
        int col = wx * 64 + ni * 8 + 2 * lm;
        *(float2*)&ao[qbase + (size_t)row0 * Dc + col] =
            make_float2(oacc[ni][0] * inv0, oacc[ni][1] * inv0);
        *(float2*)&ao[qbase + (size_t)row1 * Dc + col] =
            make_float2(oacc[ni][2] * inv1, oacc[ni][3] * inv1);
    }
}

__global__ __launch_bounds__(256) void gate_kernel(
    const float* __restrict__ hn, const float* __restrict__ Wg,
    float* __restrict__ wslot, int* __restrict__ elist, int* __restrict__ ecount)
{
    int gtid = blockIdx.x * 256 + threadIdx.x;
    int t = gtid >> 5;
    int lane = gtid & 31;
    if (t >= NT) return;

    float acc[Ec];
    #pragma unroll
    for (int e = 0; e < Ec; e++) acc[e] = 0.f;
    const float* xr = hn + (size_t)t * Dc;
    for (int d = lane; d < Dc; d += 32) {
        float xv = xr[d];
        const float* wr = Wg + (size_t)d * Ec;
        #pragma unroll
        for (int e = 0; e < Ec; e++) acc[e] = fmaf(xv, wr[e], acc[e]);
    }
    #pragma unroll
    for (int e = 0; e < Ec; e++)
        #pragma unroll
        for (int m = 16; m >= 1; m >>= 1)
            acc[e] += __shfl_xor_sync(0xffffffffu, acc[e], m);

    if (lane == 0) {
        int e0 = 0; float l0 = acc[0];
        #pragma unroll
        for (int e = 1; e < Ec; e++) if (acc[e] > l0) { l0 = acc[e]; e0 = e; }
        int e1 = -1; float l1 = -3.4e38f;
        #pragma unroll
        for (int e = 0; e < Ec; e++) {
            if (e == e0) continue;
            if (acc[e] > l1) { l1 = acc[e]; e1 = e; }
        }
        float t1 = expf(l1 - l0);
        float w0 = 1.f / (1.f + t1);
        float w1 = t1 / (1.f + t1);
        wslot[2 * t]     = w0;
        wslot[2 * t + 1] = w1;
        int p0 = atomicAdd(&ecount[e0], 1);
        elist[e0 * NT + p0] = 2 * t;
        int p1 = atomicAdd(&ecount[e1], 1);
        elist[e1 * NT + p1] = 2 * t + 1;
    }
}

__global__ __launch_bounds__(256) void combine_kernel(
    const float* __restrict__ h, const float* __restrict__ moeout,
    float* __restrict__ out)
{
    size_t i = (size_t)blockIdx.x * 256 + threadIdx.x;
    size_t t = i >> 10, d = i & 1023;
    out[i] = h[i] + moeout[(2 * t) * (size_t)Dc + d]
                  + moeout[(2 * t + 1) * (size_t)Dc + d];
}

extern "C" void kernel_launch(void* const* d_in, const int* in_sizes, int n_in,
                              void* d_out, int out_size)
{
    const float* x     = (const float*)d_in[0];
    const float* freqs = (const float*)d_in[1];
    const float* g1    = (const float*)d_in[2];
    const float* b1    = (const float*)d_in[3];
    const float* g2    = (const float*)d_in[4];
    const float* b2    = (const float*)d_in[5];
    const float* Wq    = (const float*)d_in[6];
    const float* Wdkv  = (const float*)d_in[7];
    const float* Wuk   = (const float*)d_in[8];
    const float* Wuv   = (const float*)d_in[9];
    const float* Wo    = (const float*)d_in[10];
    const float* Wg    = (const float*)d_in[11];
    const float* W1    = (const float*)d_in[12];
    const float* W2    = (const float*)d_in[13];
    float* out = (float*)d_out;

    void* bufp = nullptr;
    cudaGetSymbolAddress(&bufp, g_buf);
    float* buf   = (float*)bufp;
    float* xn    = buf + OFF_XN;
    float* qb_   = buf + OFF_Q;
    float* kb_   = buf + OFF_K;
    float* vb_   = buf + OFF_V;
    float* lat   = buf + OFF_LAT;
    float* ao    = buf + OFF_AO;
    float* h     = buf + OFF_H;
    float* hn    = buf + OFF_HN;
    float* act   = buf + OFF_ACT;
    float* moeo  = buf + OFF_MOE;
    float* wslot = buf + OFF_WSLOT;
    int*   elist = (int*)(buf + OFF_ELIST);
    int*   ecnt  = (int*)(buf + OFF_ECNT);

    cudaFuncSetAttribute(flash_tc_kernel,
                         cudaFuncAttributeMaxDynamicSharedMemorySize, FLASH_SMEM);

    reset_kernel<<<1, 32>>>(ecnt);
    ln_kernel<<<NT, 256>>>(x, g1, b1, xn);

    tgemm_kernel<0, false><<<dim3(Dc / 128, NT / 128), 256>>>(
        xn, Wq, nullptr, qb_, NT, Dc, Dc, nullptr, nullptr, nullptr, 0, 0);
    tgemm_kernel<0, false><<<dim3(Lc / 128, NT / 128), 256>>>(
        xn, Wdkv, nullptr, lat, NT, Dc, Lc, nullptr, nullptr, nullptr, 0, 0);
    tgemm_kernel<0, false><<<dim3(Dc / 128, NT / 128), 256>>>(
        lat, Wuk, nullptr, kb_, NT, Lc, Dc, nullptr, nullptr, nullptr, 0, 0);
    tgemm_kernel<0, false><<<dim3(Dc / 128, NT / 128), 256>>>(
        lat, Wuv, nullptr, vb_, NT, Lc, Dc, nullptr, nullptr, nullptr, 0, 0);

    rope_kernel<<<(NT * (Dc / 2)) / 256, 256>>>(qb_, kb_, freqs);

    flash_tc_kernel<<<dim3(Sc / 64, Hc, Bc), 256, FLASH_SMEM>>>(qb_, kb_, vb_, ao);

    tgemm_kernel<1, false><<<dim3(Dc / 128, NT / 128), 256>>>(
        ao, Wo, x, h, NT, Dc, Dc, nullptr, nullptr, nullptr, 0, 0);

    ln_kernel<<<NT, 256>>>(h, g2, b2, hn);

    gate_kernel<<<(NT * 32) / 256, 256>>>(hn, Wg, wslot, elist, ecnt);

    tgemm_kernel<2, true><<<dim3(Fc / 128, NT / 128, Ec), 256>>>(
        hn, W1, nullptr, act, 0, Dc, Fc, elist, ecnt, nullptr, 1, (size_t)Dc * Fc);
    tgemm_kernel<3, true><<<dim3(Dc / 128, NT / 128, Ec), 256>>>(
        act, W2, nullptr, moeo, 0, Fc, Dc, elist, ecnt, wslot, 0, (size_t)Fc * Dc);

    combine_kernel<<<(NT * Dc) / 256, 256>>>(h, moeo, out);
}

// round 9
// speedup vs baseline: 2.6571x; 1.0285x over previous
#include <cuda_runtime.h>
#include <cuda_bf16.h>
#include <math.h>
#include <stdint.h>

constexpr int Bc  = 2;
constexpr int Sc  = 2048;
constexpr int Dc  = 1024;
constexpr int Lc  = 512;
constexpr int Hc  = 8;
constexpr int HDc = 128;
constexpr int Ec  = 8;
constexpr int Fc  = 4096;
constexpr int NT  = Bc * Sc;

constexpr size_t OFF_XN    = 0;
constexpr size_t OFF_Q     = OFF_XN    + (size_t)NT * Dc;
constexpr size_t OFF_K     = OFF_Q     + (size_t)NT * Dc;
constexpr size_t OFF_V     = OFF_K     + (size_t)NT * Dc;
constexpr size_t OFF_LAT   = OFF_V     + (size_t)NT * Dc;
constexpr size_t OFF_AO    = OFF_LAT   + (size_t)NT * Lc;
constexpr size_t OFF_H     = OFF_AO    + (size_t)NT * Dc;
constexpr size_t OFF_HN    = OFF_H     + (size_t)NT * Dc;
constexpr size_t OFF_ACT   = OFF_HN    + (size_t)NT * Dc;
constexpr size_t OFF_MOE   = OFF_ACT   + (size_t)2 * NT * Fc;
constexpr size_t OFF_WSLOT = OFF_MOE   + (size_t)2 * NT * Dc;
constexpr size_t OFF_ELIST = OFF_WSLOT + (size_t)2 * NT;
constexpr size_t OFF_ECNT  = OFF_ELIST + (size_t)Ec * NT;
constexpr size_t BUF_TOTAL = OFF_ECNT + 64;

__device__ float g_buf[BUF_TOTAL];

__global__ void reset_kernel(int* ecount) {
    if (threadIdx.x < Ec) ecount[threadIdx.x] = 0;
}

__global__ __launch_bounds__(256) void ln_kernel(
    const float* __restrict__ x, const float* __restrict__ g,
    const float* __restrict__ b, float* __restrict__ y)
{
    int t = blockIdx.x;
    int tid = threadIdx.x;
    const float* xr = x + (size_t)t * Dc;
    float s = 0.f, s2 = 0.f;
    #pragma unroll
    for (int i = tid; i < Dc; i += 256) { float v = xr[i]; s += v; s2 += v * v; }
    __shared__ float sh[2][256];
    sh[0][tid] = s; sh[1][tid] = s2;
    __syncthreads();
    for (int st = 128; st > 0; st >>= 1) {
        if (tid < st) { sh[0][tid] += sh[0][tid + st]; sh[1][tid] += sh[1][tid + st]; }
        __syncthreads();
    }
    float mu   = sh[0][0] * (1.f / Dc);
    float var  = sh[1][0] * (1.f / Dc) - mu * mu;
    float rstd = rsqrtf(var + 1e-5f);
    float* yr = y + (size_t)t * Dc;
    #pragma unroll
    for (int i = tid; i < Dc; i += 256)
        yr[i] = (xr[i] - mu) * rstd * g[i] + b[i];
}

// split a pair of fp32 into bf16x2 hi + bf16x2 lo  (first arg in low half)
__device__ __forceinline__ void split2(float x0, float x1, uint32_t& hi, uint32_t& lo) {
    uint32_t h;
    asm("cvt.rn.bf16x2.f32 %0, %1, %2;" : "=r"(h) : "f"(x1), "f"(x0));
    float h0 = __uint_as_float(h << 16);
    float h1 = __uint_as_float(h & 0xffff0000u);
    uint32_t l;
    asm("cvt.rn.bf16x2.f32 %0, %1, %2;" : "=r"(l) : "f"(x1 - h1), "f"(x0 - h0));
    hi = h; lo = l;
}

__device__ __forceinline__ void mma_bf16(float* d, const uint32_t* a, const uint32_t* b) {
    asm volatile(
        "mma.sync.aligned.m16n8k16.row.col.f32.bf16.bf16.f32 "
        "{%0,%1,%2,%3}, {%4,%5,%6,%7}, {%8,%9}, {%0,%1,%2,%3};"
        : "+f"(d[0]), "+f"(d[1]), "+f"(d[2]), "+f"(d[3])
        : "r"(a[0]), "r"(a[1]), "r"(a[2]), "r"(a[3]), "r"(b[0]), "r"(b[1]));
}

// ---------------------------------------------------------------------------
// tgemm v2 (unchanged from round 8)
// ---------------------------------------------------------------------------
constexpr int PA = 12;
constexpr int PB = 136;

template <int EPI, bool GATHER>
__global__ __launch_bounds__(256, 2) void tgemm_kernel(
    const float* __restrict__ A, const float* __restrict__ B,
    const float* __restrict__ resid, float* __restrict__ C,
    int M, int K, int N,
    const int* __restrict__ elist, const int* __restrict__ ecount,
    const float* __restrict__ wslot, int ashift, size_t bExpertStride)
{
    __shared__ uint32_t Ahi[128][PA], Alo[128][PA];
    __shared__ uint32_t Bhi[8][PB],   Blo[8][PB];

    const int tid  = threadIdx.x;
    const int warp = tid >> 5;
    const int lane = tid & 31;
    const int wy = warp & 1;
    const int wx = warp >> 1;
    const int mW = wy * 64;
    const int nW = wx * 32;
    const int g  = lane >> 2;
    const int lm = lane & 3;

    const int n0 = blockIdx.x * 128;

    int e = 0, cnt = 0, rt = 0, m0 = 0;
    const float* Bbase = B;
    if (GATHER) {
        e = blockIdx.z;
        cnt = ecount[e];
        rt = blockIdx.y * 128;
        if (rt >= cnt) return;
        Bbase = B + (size_t)e * bExpertStride;
    } else {
        m0 = blockIdx.y * 128;
    }

    const int arow  = tid >> 1;
    const int acolg = (tid & 1) * 8;
    const int akp0  = (tid & 1) * 4;
    const int bkp   = tid >> 5;
    const int bn    = (tid & 31) * 4;

    const float* aptr;
    bool avalid = true;
    if (GATHER) {
        int gr = rt + arow;
        avalid = gr < cnt;
        int slot = avalid ? elist[e * NT + gr] : 0;
        aptr = A + (size_t)(slot >> ashift) * K + acolg;
    } else {
        aptr = A + (size_t)(m0 + arow) * K + acolg;
    }
    const float* bptr = Bbase + n0 + bn;

    float acc[4][4][4];
    #pragma unroll
    for (int i = 0; i < 4; i++)
        #pragma unroll
        for (int j = 0; j < 4; j++)
            #pragma unroll
            for (int c = 0; c < 4; c++) acc[i][j][c] = 0.f;

    const int KT = K >> 4;
    const float4 fz = make_float4(0.f, 0.f, 0.f, 0.f);

    float4 a0 = avalid ? *(const float4*)(aptr)     : fz;
    float4 a1 = avalid ? *(const float4*)(aptr + 4) : fz;
    float4 b0v = *(const float4*)(bptr + (size_t)(2 * bkp) * N);
    float4 b1v = *(const float4*)(bptr + (size_t)(2 * bkp + 1) * N);

    for (int kt = 0; kt < KT; kt++) {
        if (kt > 0) __syncthreads();
        {
            uint32_t h, l;
            uint4 vh, vl;
            split2(a0.x, a0.y, h, l); vh.x = h; vl.x = l;
            split2(a0.z, a0.w, h, l); vh.y = h; vl.y = l;
            split2(a1.x, a1.y, h, l); vh.z = h; vl.z = l;
            split2(a1.z, a1.w, h, l); vh.w = h; vl.w = l;
            *(uint4*)&Ahi[arow][akp0] = vh;
            *(uint4*)&Alo[arow][akp0] = vl;
            split2(b0v.x, b1v.x, h, l); vh.x = h; vl.x = l;
            split2(b0v.y, b1v.y, h, l); vh.y = h; vl.y = l;
            split2(b0v.z, b1v.z, h, l); vh.z = h; vl.z = l;
            split2(b0v.w, b1v.w, h, l); vh.w = h; vl.w = l;
            *(uint4*)&Bhi[bkp][bn] = vh;
            *(uint4*)&Blo[bkp][bn] = vl;
        }
        __syncthreads();

        if (kt + 1 < KT) {
            int k0 = (kt + 1) * 16;
            a0 = avalid ? *(const float4*)(aptr + k0)     : fz;
            a1 = avalid ? *(const float4*)(aptr + k0 + 4) : fz;
            b0v = *(const float4*)(bptr + (size_t)(k0 + 2 * bkp) * N);
            b1v = *(const float4*)(bptr + (size_t)(k0 + 2 * bkp + 1) * N);
        }

        uint32_t ahi[4][4], alo[4][4];
        #pragma unroll
        for (int mi = 0; mi < 4; mi++) {
            int r = mW + mi * 16 + g;
            ahi[mi][0] = Ahi[r    ][lm];
            ahi[mi][1] = Ahi[r + 8][lm];
            ahi[mi][2] = Ahi[r    ][lm + 4];
            ahi[mi][3] = Ahi[r + 8][lm + 4];
            alo[mi][0] = Alo[r    ][lm];
            alo[mi][1] = Alo[r + 8][lm];
            alo[mi][2] = Alo[r    ][lm + 4];
            alo[mi][3] = Alo[r + 8][lm + 4];
        }
        #pragma unroll
        for (int ni = 0; ni < 4; ni++) {
            int c = nW + ni * 8 + g;
            uint32_t bhi[2], blo[2];
            bhi[0] = Bhi[lm    ][c];
            bhi[1] = Bhi[lm + 4][c];
            blo[0] = Blo[lm    ][c];
            blo[1] = Blo[lm + 4][c];
            #pragma unroll
            for (int mi = 0; mi < 4; mi++) {
                mma_bf16(acc[mi][ni], ahi[mi], bhi);
                mma_bf16(acc[mi][ni], ahi[mi], blo);
                mma_bf16(acc[mi][ni], alo[mi], bhi);
            }
        }
    }

    #pragma unroll
    for (int mi = 0; mi < 4; mi++) {
        int r0 = mW + mi * 16 + g;
        int r1 = r0 + 8;
        size_t crow0, crow1;
        bool v0 = true, v1 = true;
        float w0 = 1.f, w1 = 1.f;
        if (GATHER) {
            int g0 = rt + r0, g1 = rt + r1;
            v0 = g0 < cnt; v1 = g1 < cnt;
            int s0 = v0 ? elist[e * NT + g0] : 0;
            int s1 = v1 ? elist[e * NT + g1] : 0;
            crow0 = (size_t)s0 * N;
            crow1 = (size_t)s1 * N;
            if (EPI == 3) { w0 = v0 ? wslot[s0] : 0.f; w1 = v1 ? wslot[s1] : 0.f; }
        } else {
            crow0 = (size_t)(m0 + r0) * N;
            crow1 = (size_t)(m0 + r1) * N;
        }
        #pragma unroll
        for (int ni = 0; ni < 4; ni++) {
            int col = n0 + nW + ni * 8 + 2 * lm;
            float x0 = acc[mi][ni][0], x1 = acc[mi][ni][1];
            float x2 = acc[mi][ni][2], x3 = acc[mi][ni][3];
            if (EPI == 1) {
                const float* rp0 = resid + crow0 + col;
                const float* rp1 = resid + crow1 + col;
                x0 += rp0[0]; x1 += rp0[1];
                x2 += rp1[0]; x3 += rp1[1];
            } else if (EPI == 2) {
                x0 = x0 / (1.f + __expf(-x0));
                x1 = x1 / (1.f + __expf(-x1));
                x2 = x2 / (1.f + __expf(-x2));
                x3 = x3 / (1.f + __expf(-x3));
            } else if (EPI == 3) {
                x0 *= w0; x1 *= w0; x2 *= w1; x3 *= w1;
            }
            if (v0) *(float2*)&C[crow0 + col] = make_float2(x0, x1);
            if (v1) *(float2*)&C[crow1 + col] = make_float2(x2, x3);
        }
    }
}

__global__ __launch_bounds__(256) void rope_kernel(
    float* __restrict__ q, float* __restrict__ k, const float* __restrict__ freqs)
{
    int p = blockIdx.x * 256 + threadIdx.x;
    int t = p >> 9;
    int r = p & 511;
    int hh = r >> 6;
    int i  = r & 63;
    int s  = t & (Sc - 1);
    float f = freqs[s * 64 + i];
    float c = cosf(f), sn = sinf(f);
    size_t base = (size_t)t * Dc + hh * HDc + 2 * i;
    float e = q[base], o = q[base + 1];
    q[base] = e * c - o * sn; q[base + 1] = e * sn + o * c;
    e = k[base]; o = k[base + 1];
    k[base] = e * c - o * sn; k[base + 1] = e * sn + o * c;
}

// ---------------------------------------------------------------------------
// Flash attention v2: pre-split bf16x2 smem everywhere.
// Q/K: [64 rows][68] kpair-major; V: [32 keypairs][136]; P: [64 rows][36].
// 8 warps: wy = warp>>1 (4 in M), wx = warp&1 (2 in N).
// ---------------------------------------------------------------------------
constexpr int QKP = 68;     // Q/K row stride (u32 kpairs; 64 used)
constexpr int VP  = 136;    // V row stride (u32; 128 used)
constexpr int PP  = 36;     // P row stride (u32 kpairs; 32 used)
constexpr int FQH = 0;
constexpr int FQL = FQH + 64 * QKP;
constexpr int FKH = FQL + 64 * QKP;
constexpr int FKL = FKH + 64 * QKP;
constexpr int FVH = FKL + 64 * QKP;
constexpr int FVL = FVH + 32 * VP;
constexpr int FPH = FVL + 32 * VP;
constexpr int FPL = FPH + 64 * PP;
constexpr int FRM = FPL + 64 * PP;
constexpr int FRS = FRM + 128;
constexpr int FLASH_SMEM = (FRS + 128) * 4;

__global__ __launch_bounds__(256) void flash_tc_kernel(
    const float* __restrict__ q, const float* __restrict__ k,
    const float* __restrict__ v, float* __restrict__ ao)
{
    extern __shared__ uint32_t smu[];
    uint32_t* QH = smu + FQH;
    uint32_t* QL = smu + FQL;
    uint32_t* KH = smu + FKH;
    uint32_t* KL = smu + FKL;
    uint32_t* VH = smu + FVH;
    uint32_t* VL = smu + FVL;
    uint32_t* PH = smu + FPH;
    uint32_t* PL = smu + FPL;
    float* RM = (float*)(smu + FRM);
    float* RS = (float*)(smu + FRS);

    const int tid  = threadIdx.x;
    const int warp = tid >> 5;
    const int lane = tid & 31;
    const int wy = warp >> 1;
    const int wx = warp & 1;
    const int g  = lane >> 2;
    const int lm = lane & 3;

    const int qb = blockIdx.x, hh = blockIdx.y, b = blockIdx.z;
    const size_t qbase = ((size_t)(b * Sc + qb * 64)) * Dc + hh * HDc;
    const float scale = 0.08838834764831845f;

    const int row0 = wy * 16 + g;
    const int row1 = row0 + 8;

    // ---- load Q, scale, split once ----
    #pragma unroll
    for (int i = 0; i < 8; i++) {
        int li = tid + i * 256;
        int r = li >> 5, c = (li & 31) * 4;
        float4 val = *(const float4*)(q + qbase + (size_t)r * Dc + c);
        uint32_t h, l;
        split2(val.x * scale, val.y * scale, h, l);
        QH[r * QKP + c / 2] = h; QL[r * QKP + c / 2] = l;
        split2(val.z * scale, val.w * scale, h, l);
        QH[r * QKP + c / 2 + 1] = h; QL[r * QKP + c / 2 + 1] = l;
    }

    float oacc[8][4];
    #pragma unroll
    for (int ni = 0; ni < 8; ni++)
        #pragma unroll
        for (int c = 0; c < 4; c++) oacc[ni][c] = 0.f;
    float m0s = -1e30f, m1s = -1e30f, l0s = 0.f, l1s = 0.f;

    for (int kb = 0; kb <= qb; kb++) {
        const size_t kbase = ((size_t)(b * Sc + kb * 64)) * Dc + hh * HDc;
        // K: split per feature pair, [key][kpair]
        #pragma unroll
        for (int i = 0; i < 8; i++) {
            int li = tid + i * 256;
            int r = li >> 5, c = (li & 31) * 4;
            float4 kv = *(const float4*)(k + kbase + (size_t)r * Dc + c);
            uint32_t h, l;
            split2(kv.x, kv.y, h, l);
            KH[r * QKP + c / 2] = h; KL[r * QKP + c / 2] = l;
            split2(kv.z, kv.w, h, l);
            KH[r * QKP + c / 2 + 1] = h; KL[r * QKP + c / 2 + 1] = l;
        }
        // V: split across key-row pairs, [keypair][hd]
        #pragma unroll
        for (int i = 0; i < 4; i++) {
            int li = tid + i * 256;
            int j = li >> 5, c = (li & 31) * 4;
            float4 v0 = *(const float4*)(v + kbase + (size_t)(2 * j) * Dc + c);
            float4 v1 = *(const float4*)(v + kbase + (size_t)(2 * j + 1) * Dc + c);
            uint32_t h, l;
            uint4 vh, vl;
            split2(v0.x, v1.x, h, l); vh.x = h; vl.x = l;
            split2(v0.y, v1.y, h, l); vh.y = h; vl.y = l;
            split2(v0.z, v1.z, h, l); vh.z = h; vl.z = l;
            split2(v0.w, v1.w, h, l); vh.w = h; vl.w = l;
            *(uint4*)&VH[j * VP + c] = vh;
            *(uint4*)&VL[j * VP + c] = vl;
        }
        __syncthreads();

        // ---- S = Q @ K^T ----
        float sacc[4][4];
        #pragma unroll
        for (int ni = 0; ni < 4; ni++)
            #pragma unroll
            for (int c = 0; c < 4; c++) sacc[ni][c] = 0.f;

        #pragma unroll
        for (int ks = 0; ks < 8; ks++) {
            int kpb = ks * 8;
            uint32_t ahi[4], alo[4];
            ahi[0] = QH[row0 * QKP + kpb + lm];
            ahi[1] = QH[row1 * QKP + kpb + lm];
            ahi[2] = QH[row0 * QKP + kpb + lm + 4];
            ahi[3] = QH[row1 * QKP + kpb + lm + 4];
            alo[0] = QL[row0 * QKP + kpb + lm];
            alo[1] = QL[row1 * QKP + kpb + lm];
            alo[2] = QL[row0 * QKP + kpb + lm + 4];
            alo[3] = QL[row1 * QKP + kpb + lm + 4];
            #pragma unroll
            for (int ni = 0; ni < 4; ni++) {
                int ck = wx * 32 + ni * 8 + g;
                uint32_t bhi[2], blo[2];
                bhi[0] = KH[ck * QKP + kpb + lm];
                bhi[1] = KH[ck * QKP + kpb + lm + 4];
                blo[0] = KL[ck * QKP + kpb + lm];
                blo[1] = KL[ck * QKP + kpb + lm + 4];
                mma_bf16(sacc[ni], ahi, bhi);
                mma_bf16(sacc[ni], ahi, blo);
                mma_bf16(sacc[ni], alo, bhi);
            }
        }

        // ---- causal mask ----
        if (kb == qb) {
            int qa0 = qb * 64 + row0;
            int qa1 = qb * 64 + row1;
            #pragma unroll
            for (int ni = 0; ni < 4; ni++) {
                int ka = kb * 64 + wx * 32 + ni * 8 + 2 * lm;
                if (ka     > qa0) sacc[ni][0] = -1e30f;
                if (ka + 1 > qa0) sacc[ni][1] = -1e30f;
                if (ka     > qa1) sacc[ni][2] = -1e30f;
                if (ka + 1 > qa1) sacc[ni][3] = -1e30f;
            }
        }

        // ---- online softmax ----
        float rm0 = -1e30f, rm1 = -1e30f;
        #pragma unroll
        for (int ni = 0; ni < 4; ni++) {
            rm0 = fmaxf(rm0, fmaxf(sacc[ni][0], sacc[ni][1]));
            rm1 = fmaxf(rm1, fmaxf(sacc[ni][2], sacc[ni][3]));
        }
        rm0 = fmaxf(rm0, __shfl_xor_sync(0xffffffffu, rm0, 1));
        rm0 = fmaxf(rm0, __shfl_xor_sync(0xffffffffu, rm0, 2));
        rm1 = fmaxf(rm1, __shfl_xor_sync(0xffffffffu, rm1, 1));
        rm1 = fmaxf(rm1, __shfl_xor_sync(0xffffffffu, rm1, 2));
        if (lm == 0) {
            RM[row0 * 2 + wx] = rm0;
            RM[row1 * 2 + wx] = rm1;
        }
        __syncthreads();

        float mn0 = fmaxf(m0s, fmaxf(RM[row0 * 2], RM[row0 * 2 + 1]));
        float mn1 = fmaxf(m1s, fmaxf(RM[row1 * 2], RM[row1 * 2 + 1]));

        float ps0 = 0.f, ps1 = 0.f;
        #pragma unroll
        for (int ni = 0; ni < 4; ni++) {
            float p0 = __expf(sacc[ni][0] - mn0);
            float p1 = __expf(sacc[ni][1] - mn0);
            float p2 = __expf(sacc[ni][2] - mn1);
            float p3 = __expf(sacc[ni][3] - mn1);
            ps0 += p0 + p1; ps1 += p2 + p3;
            int kpw = wx * 16 + ni * 4 + lm;
            uint32_t h, l;
            split2(p0, p1, h, l);
            PH[row0 * PP + kpw] = h; PL[row0 * PP + kpw] = l;
            split2(p2, p3, h, l);
            PH[row1 * PP + kpw] = h; PL[row1 * PP + kpw] = l;
        }
        ps0 += __shfl_xor_sync(0xffffffffu, ps0, 1);
        ps0 += __shfl_xor_sync(0xffffffffu, ps0, 2);
        ps1 += __shfl_xor_sync(0xffffffffu, ps1, 1);
        ps1 += __shfl_xor_sync(0xffffffffu, ps1, 2);
        if (lm == 0) {
            RS[row0 * 2 + wx] = ps0;
            RS[row1 * 2 + wx] = ps1;
        }
        __syncthreads();

        float sc0 = __expf(m0s - mn0);
        float sc1 = __expf(m1s - mn1);
        l0s = l0s * sc0 + RS[row0 * 2] + RS[row0 * 2 + 1];
        l1s = l1s * sc1 + RS[row1 * 2] + RS[row1 * 2 + 1];
        m0s = mn0; m1s = mn1;
        #pragma unroll
        for (int ni = 0; ni < 8; ni++) {
            oacc[ni][0] *= sc0; oacc[ni][1] *= sc0;
            oacc[ni][2] *= sc1; oacc[ni][3] *= sc1;
        }

        // ---- O += P @ V ----
        #pragma unroll
        for (int ks = 0; ks < 4; ks++) {
            int kpb = ks * 8;
            uint32_t ahi[4], alo[4];
            ahi[0] = PH[row0 * PP + kpb + lm];
            ahi[1] = PH[row1 * PP + kpb + lm];
            ahi[2] = PH[row0 * PP + kpb + lm + 4];
            ahi[3] = PH[row1 * PP + kpb + lm + 4];
            alo[0] = PL[row0 * PP + kpb + lm];
            alo[1] = PL[row1 * PP + kpb + lm];
            alo[2] = PL[row0 * PP + kpb + lm + 4];
            alo[3] = PL[row1 * PP + kpb + lm + 4];
            #pragma unroll
            for (int ni = 0; ni < 8; ni++) {
                int vc = wx * 64 + ni * 8 + g;
                uint32_t bhi[2], blo[2];
                bhi[0] = VH[(kpb + lm)     * VP + vc];
                bhi[1] = VH[(kpb + lm + 4) * VP + vc];
                blo[0] = VL[(kpb + lm)     * VP + vc];
                blo[1] = VL[(kpb + lm + 4) * VP + vc];
                mma_bf16(oacc[ni], ahi, bhi);
                mma_bf16(oacc[ni], ahi, blo);
                mma_bf16(oacc[ni], alo, bhi);
            }
        }
        __syncthreads();
    }

    float inv0 = 1.f / l0s;
    float inv1 = 1.f / l1s;
    #pragma unroll
    for (int ni = 0; ni < 8; ni++) {
        int col = wx * 64 + ni * 8 + 2 * lm;
        *(float2*)&ao[qbase + (size_t)row0 * Dc + col] =
            make_float2(oacc[ni][0] * inv0, oacc[ni][1] * inv0);
        *(float2*)&ao[qbase + (size_t)row1 * Dc + col] =
            make_float2(oacc[ni][2] * inv1, oacc[ni][3] * inv1);
    }
}

__global__ __launch_bounds__(256) void gate_kernel(
    const float* __restrict__ hn, const float* __restrict__ Wg,
    float* __restrict__ wslot, int* __restrict__ elist, int* __restrict__ ecount)
{
    int gtid = blockIdx.x * 256 + threadIdx.x;
    int t = gtid >> 5;
    int lane = gtid & 31;
    if (t >= NT) return;

    float acc[Ec];
    #pragma unroll
    for (int e = 0; e < Ec; e++) acc[e] = 0.f;
    const float* xr = hn + (size_t)t * Dc;
    for (int d = lane; d < Dc; d += 32) {
        float xv = xr[d];
        const float* wr = Wg + (size_t)d * Ec;
        #pragma unroll
        for (int e = 0; e < Ec; e++) acc[e] = fmaf(xv, wr[e], acc[e]);
    }
    #pragma unroll
    for (int e = 0; e < Ec; e++)
        #pragma unroll
        for (int m = 16; m >= 1; m >>= 1)
            acc[e] += __shfl_xor_sync(0xffffffffu, acc[e], m);

    if (lane == 0) {
        int e0 = 0; float l0 = acc[0];
        #pragma unroll
        for (int e = 1; e < Ec; e++) if (acc[e] > l0) { l0 = acc[e]; e0 = e; }
        int e1 = -1; float l1 = -3.4e38f;
        #pragma unroll
        for (int e = 0; e < Ec; e++) {
            if (e == e0) continue;
            if (acc[e] > l1) { l1 = acc[e]; e1 = e; }
        }
        float t1 = expf(l1 - l0);
        float w0 = 1.f / (1.f + t1);
        float w1 = t1 / (1.f + t1);
        wslot[2 * t]     = w0;
        wslot[2 * t + 1] = w1;
        int p0 = atomicAdd(&ecount[e0], 1);
        elist[e0 * NT + p0] = 2 * t;
        int p1 = atomicAdd(&ecount[e1], 1);
        elist[e1 * NT + p1] = 2 * t + 1;
    }
}

__global__ __launch_bounds__(256) void combine_kernel(
    const float* __restrict__ h, const float* __restrict__ moeout,
    float* __restrict__ out)
{
    size_t i = (size_t)blockIdx.x * 256 + threadIdx.x;
    size_t t = i >> 10, d = i & 1023;
    out[i] = h[i] + moeout[(2 * t) * (size_t)Dc + d]
                  + moeout[(2 * t + 1) * (size_t)Dc + d];
}

extern "C" void kernel_launch(void* const* d_in, const int* in_sizes, int n_in,
                              void* d_out, int out_size)
{
    const float* x     = (const float*)d_in[0];
    const float* freqs = (const float*)d_in[1];
    const float* g1    = (const float*)d_in[2];
    const float* b1    = (const float*)d_in[3];
    const float* g2    = (const float*)d_in[4];
    const float* b2    = (const float*)d_in[5];
    const float* Wq    = (const float*)d_in[6];
    const float* Wdkv  = (const float*)d_in[7];
    const float* Wuk   = (const float*)d_in[8];
    const float* Wuv   = (const float*)d_in[9];
    const float* Wo    = (const float*)d_in[10];
    const float* Wg    = (const float*)d_in[11];
    const float* W1    = (const float*)d_in[12];
    const float* W2    = (const float*)d_in[13];
    float* out = (float*)d_out;

    void* bufp = nullptr;
    cudaGetSymbolAddress(&bufp, g_buf);
    float* buf   = (float*)bufp;
    float* xn    = buf + OFF_XN;
    float* qb_   = buf + OFF_Q;
    float* kb_   = buf + OFF_K;
    float* vb_   = buf + OFF_V;
    float* lat   = buf + OFF_LAT;
    float* ao    = buf + OFF_AO;
    float* h     = buf + OFF_H;
    float* hn    = buf + OFF_HN;
    float* act   = buf + OFF_ACT;
    float* moeo  = buf + OFF_MOE;
    float* wslot = buf + OFF_WSLOT;
    int*   elist = (int*)(buf + OFF_ELIST);
    int*   ecnt  = (int*)(buf + OFF_ECNT);

    cudaFuncSetAttribute(flash_tc_kernel,
                         cudaFuncAttributeMaxDynamicSharedMemorySize, FLASH_SMEM);

    reset_kernel<<<1, 32>>>(ecnt);
    ln_kernel<<<NT, 256>>>(x, g1, b1, xn);

    tgemm_kernel<0, false><<<dim3(Dc / 128, NT / 128), 256>>>(
        xn, Wq, nullptr, qb_, NT, Dc, Dc, nullptr, nullptr, nullptr, 0, 0);
    tgemm_kernel<0, false><<<dim3(Lc / 128, NT / 128), 256>>>(
        xn, Wdkv, nullptr, lat, NT, Dc, Lc, nullptr, nullptr, nullptr, 0, 0);
    tgemm_kernel<0, false><<<dim3(Dc / 128, NT / 128), 256>>>(
        lat, Wuk, nullptr, kb_, NT, Lc, Dc, nullptr, nullptr, nullptr, 0, 0);
    tgemm_kernel<0, false><<<dim3(Dc / 128, NT / 128), 256>>>(
        lat, Wuv, nullptr, vb_, NT, Lc, Dc, nullptr, nullptr, nullptr, 0, 0);

    rope_kernel<<<(NT * (Dc / 2)) / 256, 256>>>(qb_, kb_, freqs);

    flash_tc_kernel<<<dim3(Sc / 64, Hc, Bc), 256, FLASH_SMEM>>>(qb_, kb_, vb_, ao);

    tgemm_kernel<1, false><<<dim3(Dc / 128, NT / 128), 256>>>(
        ao, Wo, x, h, NT, Dc, Dc, nullptr, nullptr, nullptr, 0, 0);

    ln_kernel<<<NT, 256>>>(h, g2, b2, hn);

    gate_kernel<<<(NT * 32) / 256, 256>>>(hn, Wg, wslot, elist, ecnt);

    tgemm_kernel<2, true><<<dim3(Fc / 128, NT / 128, Ec), 256>>>(
        hn, W1, nullptr, act, 0, Dc, Fc, elist, ecnt, nullptr, 1, (size_t)Dc * Fc);
    tgemm_kernel<3, true><<<dim3(Dc / 128, NT / 128, Ec), 256>>>(
        act, W2, nullptr, moeo, 0, Fc, Dc, elist, ecnt, wslot, 0, (size_t)Fc * Dc);

    combine_kernel<<<(NT * Dc) / 256, 256>>>(h, moeo, out);
}

// round 10
// speedup vs baseline: 2.9617x; 1.1146x over previous
#include <cuda_runtime.h>
#include <cuda_bf16.h>
#include <math.h>
#include <stdint.h>

constexpr int Bc  = 2;
constexpr int Sc  = 2048;
constexpr int Dc  = 1024;
constexpr int Lc  = 512;
constexpr int Hc  = 8;
constexpr int HDc = 128;
constexpr int Ec  = 8;
constexpr int Fc  = 4096;
constexpr int NT  = Bc * Sc;

constexpr size_t OFF_XN    = 0;
constexpr size_t OFF_Q     = OFF_XN    + (size_t)NT * Dc;
constexpr size_t OFF_K     = OFF_Q     + (size_t)NT * Dc;
constexpr size_t OFF_V     = OFF_K     + (size_t)NT * Dc;
constexpr size_t OFF_LAT   = OFF_V     + (size_t)NT * Dc;
constexpr size_t OFF_AO    = OFF_LAT   + (size_t)NT * Lc;
constexpr size_t OFF_H     = OFF_AO    + (size_t)NT * Dc;
constexpr size_t OFF_HN    = OFF_H     + (size_t)NT * Dc;
constexpr size_t OFF_ACT   = OFF_HN    + (size_t)NT * Dc;
constexpr size_t OFF_MOE   = OFF_ACT   + (size_t)2 * NT * Fc;
constexpr size_t OFF_WSLOT = OFF_MOE   + (size_t)2 * NT * Dc;
constexpr size_t OFF_ELIST = OFF_WSLOT + (size_t)2 * NT;
constexpr size_t OFF_ECNT  = OFF_ELIST + (size_t)Ec * NT;
constexpr size_t BUF_TOTAL = OFF_ECNT + 64;

__device__ float g_buf[BUF_TOTAL];

__global__ void reset_kernel(int* ecount) {
    if (threadIdx.x < Ec) ecount[threadIdx.x] = 0;
}

__global__ __launch_bounds__(256) void ln_kernel(
    const float* __restrict__ x, const float* __restrict__ g,
    const float* __restrict__ b, float* __restrict__ y)
{
    int t = blockIdx.x;
    int tid = threadIdx.x;
    const float* xr = x + (size_t)t * Dc;
    float s = 0.f, s2 = 0.f;
    #pragma unroll
    for (int i = tid; i < Dc; i += 256) { float v = xr[i]; s += v; s2 += v * v; }
    __shared__ float sh[2][256];
    sh[0][tid] = s; sh[1][tid] = s2;
    __syncthreads();
    for (int st = 128; st > 0; st >>= 1) {
        if (tid < st) { sh[0][tid] += sh[0][tid + st]; sh[1][tid] += sh[1][tid + st]; }
        __syncthreads();
    }
    float mu   = sh[0][0] * (1.f / Dc);
    float var  = sh[1][0] * (1.f / Dc) - mu * mu;
    float rstd = rsqrtf(var + 1e-5f);
    float* yr = y + (size_t)t * Dc;
    #pragma unroll
    for (int i = tid; i < Dc; i += 256)
        yr[i] = (xr[i] - mu) * rstd * g[i] + b[i];
}

// split a pair of fp32 into bf16x2 hi + bf16x2 lo  (first arg in low half)
__device__ __forceinline__ void split2(float x0, float x1, uint32_t& hi, uint32_t& lo) {
    uint32_t h;
    asm("cvt.rn.bf16x2.f32 %0, %1, %2;" : "=r"(h) : "f"(x1), "f"(x0));
    float h0 = __uint_as_float(h << 16);
    float h1 = __uint_as_float(h & 0xffff0000u);
    uint32_t l;
    asm("cvt.rn.bf16x2.f32 %0, %1, %2;" : "=r"(l) : "f"(x1 - h1), "f"(x0 - h0));
    hi = h; lo = l;
}

__device__ __forceinline__ void mma_bf16(float* d, const uint32_t* a, const uint32_t* b) {
    asm volatile(
        "mma.sync.aligned.m16n8k16.row.col.f32.bf16.bf16.f32 "
        "{%0,%1,%2,%3}, {%4,%5,%6,%7}, {%8,%9}, {%0,%1,%2,%3};"
        : "+f"(d[0]), "+f"(d[1]), "+f"(d[2]), "+f"(d[3])
        : "r"(a[0]), "r"(a[1]), "r"(a[2]), "r"(a[3]), "r"(b[0]), "r"(b[1]));
}

// ---------------------------------------------------------------------------
// tgemm v3: double-buffered pre-split smem, ONE barrier per k-iter.
// 128x128 block tile, BK=16. 8 warps: 2(M) x 4(N); warp tile 64x32.
// EPI: 0 none, 1 +resid, 2 silu, 3 *wslot.  GATHER: rows via elist.
// Optional second (B2,C2) pair selected by blockIdx.z (non-gather only).
// ---------------------------------------------------------------------------
constexpr int PA = 12;
constexpr int PB = 136;

template <int EPI, bool GATHER>
__global__ __launch_bounds__(256, 2) void tgemm_kernel(
    const float* __restrict__ A, const float* __restrict__ B,
    const float* __restrict__ resid, float* __restrict__ C,
    int M, int K, int N,
    const int* __restrict__ elist, const int* __restrict__ ecount,
    const float* __restrict__ wslot, int ashift, size_t bExpertStride,
    const float* __restrict__ B2, float* __restrict__ C2)
{
    __shared__ uint32_t Ahi[2][128][PA], Alo[2][128][PA];
    __shared__ uint32_t Bhi[2][8][PB],   Blo[2][8][PB];

    const int tid  = threadIdx.x;
    const int warp = tid >> 5;
    const int lane = tid & 31;
    const int wy = warp & 1;
    const int wx = warp >> 1;
    const int mW = wy * 64;
    const int nW = wx * 32;
    const int g  = lane >> 2;
    const int lm = lane & 3;

    const int n0 = blockIdx.x * 128;

    int e = 0, cnt = 0, rt = 0, m0 = 0;
    const float* Bbase = B;
    float* Cw = C;
    if (GATHER) {
        e = blockIdx.z;
        cnt = ecount[e];
        rt = blockIdx.y * 128;
        if (rt >= cnt) return;
        Bbase = B + (size_t)e * bExpertStride;
    } else {
        m0 = blockIdx.y * 128;
        if (B2 != nullptr && blockIdx.z == 1) { Bbase = B2; Cw = C2; }
    }

    const int arow  = tid >> 1;
    const int acolg = (tid & 1) * 8;
    const int akp0  = (tid & 1) * 4;
    const int bkp   = tid >> 5;
    const int bn    = (tid & 31) * 4;

    const float* aptr;
    bool avalid = true;
    if (GATHER) {
        int gr = rt + arow;
        avalid = gr < cnt;
        int slot = avalid ? elist[e * NT + gr] : 0;
        aptr = A + (size_t)(slot >> ashift) * K + acolg;
    } else {
        aptr = A + (size_t)(m0 + arow) * K + acolg;
    }
    const float* bptr = Bbase + n0 + bn;

    float acc[4][4][4];
    #pragma unroll
    for (int i = 0; i < 4; i++)
        #pragma unroll
        for (int j = 0; j < 4; j++)
            #pragma unroll
            for (int c = 0; c < 4; c++) acc[i][j][c] = 0.f;

    const int KT = K >> 4;
    const float4 fz = make_float4(0.f, 0.f, 0.f, 0.f);

    // stage tile 0
    float4 a0 = avalid ? *(const float4*)(aptr)     : fz;
    float4 a1 = avalid ? *(const float4*)(aptr + 4) : fz;
    float4 b0v = *(const float4*)(bptr + (size_t)(2 * bkp) * N);
    float4 b1v = *(const float4*)(bptr + (size_t)(2 * bkp + 1) * N);

    for (int kt = 0; kt < KT; kt++) {
        const int cb = kt & 1;
        // split-store staged tile kt into buffer cb
        {
            uint32_t h, l;
            uint4 vh, vl;
            split2(a0.x, a0.y, h, l); vh.x = h; vl.x = l;
            split2(a0.z, a0.w, h, l); vh.y = h; vl.y = l;
            split2(a1.x, a1.y, h, l); vh.z = h; vl.z = l;
            split2(a1.z, a1.w, h, l); vh.w = h; vl.w = l;
            *(uint4*)&Ahi[cb][arow][akp0] = vh;
            *(uint4*)&Alo[cb][arow][akp0] = vl;
            split2(b0v.x, b1v.x, h, l); vh.x = h; vl.x = l;
            split2(b0v.y, b1v.y, h, l); vh.y = h; vl.y = l;
            split2(b0v.z, b1v.z, h, l); vh.z = h; vl.z = l;
            split2(b0v.w, b1v.w, h, l); vh.w = h; vl.w = l;
            *(uint4*)&Bhi[cb][bkp][bn] = vh;
            *(uint4*)&Blo[cb][bkp][bn] = vl;
        }
        __syncthreads();          // single barrier per iteration

        // prefetch tile kt+1 into registers (overlaps with compute)
        if (kt + 1 < KT) {
            int k0 = (kt + 1) * 16;
            a0 = avalid ? *(const float4*)(aptr + k0)     : fz;
            a1 = avalid ? *(const float4*)(aptr + k0 + 4) : fz;
            b0v = *(const float4*)(bptr + (size_t)(k0 + 2 * bkp) * N);
            b1v = *(const float4*)(bptr + (size_t)(k0 + 2 * bkp + 1) * N);
        }

        uint32_t ahi[4][4], alo[4][4];
        #pragma unroll
        for (int mi = 0; mi < 4; mi++) {
            int r = mW + mi * 16 + g;
            ahi[mi][0] = Ahi[cb][r    ][lm];
            ahi[mi][1] = Ahi[cb][r + 8][lm];
            ahi[mi][2] = Ahi[cb][r    ][lm + 4];
            ahi[mi][3] = Ahi[cb][r + 8][lm + 4];
            alo[mi][0] = Alo[cb][r    ][lm];
            alo[mi][1] = Alo[cb][r + 8][lm];
            alo[mi][2] = Alo[cb][r    ][lm + 4];
            alo[mi][3] = Alo[cb][r + 8][lm + 4];
        }
        #pragma unroll
        for (int ni = 0; ni < 4; ni++) {
            int c = nW + ni * 8 + g;
            uint32_t bhi[2], blo[2];
            bhi[0] = Bhi[cb][lm    ][c];
            bhi[1] = Bhi[cb][lm + 4][c];
            blo[0] = Blo[cb][lm    ][c];
            blo[1] = Blo[cb][lm + 4][c];
            #pragma unroll
            for (int mi = 0; mi < 4; mi++) {
                mma_bf16(acc[mi][ni], ahi[mi], bhi);
                mma_bf16(acc[mi][ni], ahi[mi], blo);
                mma_bf16(acc[mi][ni], alo[mi], bhi);
            }
        }
        // no trailing barrier: next iter stores into buf cb^1, whose readers
        // (iter kt-1 compute) are all past this iteration's barrier.
    }

    #pragma unroll
    for (int mi = 0; mi < 4; mi++) {
        int r0 = mW + mi * 16 + g;
        int r1 = r0 + 8;
        size_t crow0, crow1;
        bool v0 = true, v1 = true;
        float w0 = 1.f, w1 = 1.f;
        if (GATHER) {
            int g0 = rt + r0, g1 = rt + r1;
            v0 = g0 < cnt; v1 = g1 < cnt;
            int s0 = v0 ? elist[e * NT + g0] : 0;
            int s1 = v1 ? elist[e * NT + g1] : 0;
            crow0 = (size_t)s0 * N;
            crow1 = (size_t)s1 * N;
            if (EPI == 3) { w0 = v0 ? wslot[s0] : 0.f; w1 = v1 ? wslot[s1] : 0.f; }
        } else {
            crow0 = (size_t)(m0 + r0) * N;
            crow1 = (size_t)(m0 + r1) * N;
        }
        #pragma unroll
        for (int ni = 0; ni < 4; ni++) {
            int col = n0 + nW + ni * 8 + 2 * lm;
            float x0 = acc[mi][ni][0], x1 = acc[mi][ni][1];
            float x2 = acc[mi][ni][2], x3 = acc[mi][ni][3];
            if (EPI == 1) {
                const float* rp0 = resid + crow0 + col;
                const float* rp1 = resid + crow1 + col;
                x0 += rp0[0]; x1 += rp0[1];
                x2 += rp1[0]; x3 += rp1[1];
            } else if (EPI == 2) {
                x0 = x0 / (1.f + __expf(-x0));
                x1 = x1 / (1.f + __expf(-x1));
                x2 = x2 / (1.f + __expf(-x2));
                x3 = x3 / (1.f + __expf(-x3));
            } else if (EPI == 3) {
                x0 *= w0; x1 *= w0; x2 *= w1; x3 *= w1;
            }
            if (v0) *(float2*)&Cw[crow0 + col] = make_float2(x0, x1);
            if (v1) *(float2*)&Cw[crow1 + col] = make_float2(x2, x3);
        }
    }
}

__global__ __launch_bounds__(256) void rope_kernel(
    float* __restrict__ q, float* __restrict__ k, const float* __restrict__ freqs)
{
    int p = blockIdx.x * 256 + threadIdx.x;
    int t = p >> 9;
    int r = p & 511;
    int hh = r >> 6;
    int i  = r & 63;
    int s  = t & (Sc - 1);
    float f = freqs[s * 64 + i];
    float c = cosf(f), sn = sinf(f);
    size_t base = (size_t)t * Dc + hh * HDc + 2 * i;
    float e = q[base], o = q[base + 1];
    q[base] = e * c - o * sn; q[base + 1] = e * sn + o * c;
    e = k[base]; o = k[base + 1];
    k[base] = e * c - o * sn; k[base + 1] = e * sn + o * c;
}

// ---------------------------------------------------------------------------
// Flash attention v2 (round-9) + heavy-tiles-first scheduling
// ---------------------------------------------------------------------------
constexpr int QKP = 68;
constexpr int VP  = 136;
constexpr int PP  = 36;
constexpr int FQH = 0;
constexpr int FQL = FQH + 64 * QKP;
constexpr int FKH = FQL + 64 * QKP;
constexpr int FKL = FKH + 64 * QKP;
constexpr int FVH = FKL + 64 * QKP;
constexpr int FVL = FVH + 32 * VP;
constexpr int FPH = FVL + 32 * VP;
constexpr int FPL = FPH + 64 * PP;
constexpr int FRM = FPL + 64 * PP;
constexpr int FRS = FRM + 128;
constexpr int FLASH_SMEM = (FRS + 128) * 4;

__global__ __launch_bounds__(256) void flash_tc_kernel(
    const float* __restrict__ q, const float* __restrict__ k,
    const float* __restrict__ v, float* __restrict__ ao)
{
    extern __shared__ uint32_t smu[];
    uint32_t* QH = smu + FQH;
    uint32_t* QL = smu + FQL;
    uint32_t* KH = smu + FKH;
    uint32_t* KL = smu + FKL;
    uint32_t* VH = smu + FVH;
    uint32_t* VL = smu + FVL;
    uint32_t* PH = smu + FPH;
    uint32_t* PL = smu + FPL;
    float* RM = (float*)(smu + FRM);
    float* RS = (float*)(smu + FRS);

    const int tid  = threadIdx.x;
    const int warp = tid >> 5;
    const int lane = tid & 31;
    const int wy = warp >> 1;
    const int wx = warp & 1;
    const int g  = lane >> 2;
    const int lm = lane & 3;

    // heavy q-tiles first: reverse the qb order
    const int qb = (gridDim.x - 1) - blockIdx.x;
    const int hh = blockIdx.y, b = blockIdx.z;
    const size_t qbase = ((size_t)(b * Sc + qb * 64)) * Dc + hh * HDc;
    const float scale = 0.08838834764831845f;

    const int row0 = wy * 16 + g;
    const int row1 = row0 + 8;

    #pragma unroll
    for (int i = 0; i < 8; i++) {
        int li = tid + i * 256;
        int r = li >> 5, c = (li & 31) * 4;
        float4 val = *(const float4*)(q + qbase + (size_t)r * Dc + c);
        uint32_t h, l;
        split2(val.x * scale, val.y * scale, h, l);
        QH[r * QKP + c / 2] = h; QL[r * QKP + c / 2] = l;
        split2(val.z * scale, val.w * scale, h, l);
        QH[r * QKP + c / 2 + 1] = h; QL[r * QKP + c / 2 + 1] = l;
    }

    float oacc[8][4];
    #pragma unroll
    for (int ni = 0; ni < 8; ni++)
        #pragma unroll
        for (int c = 0; c < 4; c++) oacc[ni][c] = 0.f;
    float m0s = -1e30f, m1s = -1e30f, l0s = 0.f, l1s = 0.f;

    for (int kb = 0; kb <= qb; kb++) {
        const size_t kbase = ((size_t)(b * Sc + kb * 64)) * Dc + hh * HDc;
        #pragma unroll
        for (int i = 0; i < 8; i++) {
            int li = tid + i * 256;
            int r = li >> 5, c = (li & 31) * 4;
            float4 kv = *(const float4*)(k + kbase + (size_t)r * Dc + c);
            uint32_t h, l;
            split2(kv.x, kv.y, h, l);
            KH[r * QKP + c / 2] = h; KL[r * QKP + c / 2] = l;
            split2(kv.z, kv.w, h, l);
            KH[r * QKP + c / 2 + 1] = h; KL[r * QKP + c / 2 + 1] = l;
        }
        #pragma unroll
        for (int i = 0; i < 4; i++) {
            int li = tid + i * 256;
            int j = li >> 5, c = (li & 31) * 4;
            float4 v0 = *(const float4*)(v + kbase + (size_t)(2 * j) * Dc + c);
            float4 v1 = *(const float4*)(v + kbase + (size_t)(2 * j + 1) * Dc + c);
            uint32_t h, l;
            uint4 vh, vl;
            split2(v0.x, v1.x, h, l); vh.x = h; vl.x = l;
            split2(v0.y, v1.y, h, l); vh.y = h; vl.y = l;
            split2(v0.z, v1.z, h, l); vh.z = h; vl.z = l;
            split2(v0.w, v1.w, h, l); vh.w = h; vl.w = l;
            *(uint4*)&VH[j * VP + c] = vh;
            *(uint4*)&VL[j * VP + c] = vl;
        }
        __syncthreads();

        float sacc[4][4];
        #pragma unroll
        for (int ni = 0; ni < 4; ni++)
            #pragma unroll
            for (int c = 0; c < 4; c++) sacc[ni][c] = 0.f;

        #pragma unroll
        for (int ks = 0; ks < 8; ks++) {
            int kpb = ks * 8;
            uint32_t ahi[4], alo[4];
            ahi[0] = QH[row0 * QKP + kpb + lm];
            ahi[1] = QH[row1 * QKP + kpb + lm];
            ahi[2] = QH[row0 * QKP + kpb + lm + 4];
            ahi[3] = QH[row1 * QKP + kpb + lm + 4];
            alo[0] = QL[row0 * QKP + kpb + lm];
            alo[1] = QL[row1 * QKP + kpb + lm];
            alo[2] = QL[row0 * QKP + kpb + lm + 4];
            alo[3] = QL[row1 * QKP + kpb + lm + 4];
            #pragma unroll
            for (int ni = 0; ni < 4; ni++) {
                int ck = wx * 32 + ni * 8 + g;
                uint32_t bhi[2], blo[2];
                bhi[0] = KH[ck * QKP + kpb + lm];
                bhi[1] = KH[ck * QKP + kpb + lm + 4];
                blo[0] = KL[ck * QKP + kpb + lm];
                blo[1] = KL[ck * QKP + kpb + lm + 4];
                mma_bf16(sacc[ni], ahi, bhi);
                mma_bf16(sacc[ni], ahi, blo);
                mma_bf16(sacc[ni], alo, bhi);
            }
        }

        if (kb == qb) {
            int qa0 = qb * 64 + row0;
            int qa1 = qb * 64 + row1;
            #pragma unroll
            for (int ni = 0; ni < 4; ni++) {
                int ka = kb * 64 + wx * 32 + ni * 8 + 2 * lm;
                if (ka     > qa0) sacc[ni][0] = -1e30f;
                if (ka + 1 > qa0) sacc[ni][1] = -1e30f;
                if (ka     > qa1) sacc[ni][2] = -1e30f;
                if (ka + 1 > qa1) sacc[ni][3] = -1e30f;
            }
        }

        float rm0 = -1e30f, rm1 = -1e30f;
        #pragma unroll
        for (int ni = 0; ni < 4; ni++) {
            rm0 = fmaxf(rm0, fmaxf(sacc[ni][0], sacc[ni][1]));
            rm1 = fmaxf(rm1, fmaxf(sacc[ni][2], sacc[ni][3]));
        }
        rm0 = fmaxf(rm0, __shfl_xor_sync(0xffffffffu, rm0, 1));
        rm0 = fmaxf(rm0, __shfl_xor_sync(0xffffffffu, rm0, 2));
        rm1 = fmaxf(rm1, __shfl_xor_sync(0xffffffffu, rm1, 1));
        rm1 = fmaxf(rm1, __shfl_xor_sync(0xffffffffu, rm1, 2));
        if (lm == 0) {
            RM[row0 * 2 + wx] = rm0;
            RM[row1 * 2 + wx] = rm1;
        }
        __syncthreads();

        float mn0 = fmaxf(m0s, fmaxf(RM[row0 * 2], RM[row0 * 2 + 1]));
        float mn1 = fmaxf(m1s, fmaxf(RM[row1 * 2], RM[row1 * 2 + 1]));

        float ps0 = 0.f, ps1 = 0.f;
        #pragma unroll
        for (int ni = 0; ni < 4; ni++) {
            float p0 = __expf(sacc[ni][0] - mn0);
            float p1 = __expf(sacc[ni][1] - mn0);
            float p2 = __expf(sacc[ni][2] - mn1);
            float p3 = __expf(sacc[ni][3] - mn1);
            ps0 += p0 + p1; ps1 += p2 + p3;
            int kpw = wx * 16 + ni * 4 + lm;
            uint32_t h, l;
            split2(p0, p1, h, l);
            PH[row0 * PP + kpw] = h; PL[row0 * PP + kpw] = l;
            split2(p2, p3, h, l);
            PH[row1 * PP + kpw] = h; PL[row1 * PP + kpw] = l;
        }
        ps0 += __shfl_xor_sync(0xffffffffu, ps0, 1);
        ps0 += __shfl_xor_sync(0xffffffffu, ps0, 2);
        ps1 += __shfl_xor_sync(0xffffffffu, ps1, 1);
        ps1 += __shfl_xor_sync(0xffffffffu, ps1, 2);
        if (lm == 0) {
            RS[row0 * 2 + wx] = ps0;
            RS[row1 * 2 + wx] = ps1;
        }
        __syncthreads();

        float sc0 = __expf(m0s - mn0);
        float sc1 = __expf(m1s - mn1);
        l0s = l0s * sc0 + RS[row0 * 2] + RS[row0 * 2 + 1];
        l1s = l1s * sc1 + RS[row1 * 2] + RS[row1 * 2 + 1];
        m0s = mn0; m1s = mn1;
        #pragma unroll
        for (int ni = 0; ni < 8; ni++) {
            oacc[ni][0] *= sc0; oacc[ni][1] *= sc0;
            oacc[ni][2] *= sc1; oacc[ni][3] *= sc1;
        }

        #pragma unroll
        for (int ks = 0; ks < 4; ks++) {
            int kpb = ks * 8;
            uint32_t ahi[4], alo[4];
            ahi[0] = PH[row0 * PP + kpb + lm];
            ahi[1] = PH[row1 * PP + kpb + lm];
            ahi[2] = PH[row0 * PP + kpb + lm + 4];
            ahi[3] = PH[row1 * PP + kpb + lm + 4];
            alo[0] = PL[row0 * PP + kpb + lm];
            alo[1] = PL[row1 * PP + kpb + lm];
            alo[2] = PL[row0 * PP + kpb + lm + 4];
            alo[3] = PL[row1 * PP + kpb + lm + 4];
            #pragma unroll
            for (int ni = 0; ni < 8; ni++) {
                int vc = wx * 64 + ni * 8 + g;
                uint32_t bhi[2], blo[2];
                bhi[0] = VH[(kpb + lm)     * VP + vc];
                bhi[1] = VH[(kpb + lm + 4) * VP + vc];
                blo[0] = VL[(kpb + lm)     * VP + vc];
                blo[1] = VL[(kpb + lm + 4) * VP + vc];
                mma_bf16(oacc[ni], ahi, bhi);
                mma_bf16(oacc[ni], ahi, blo);
                mma_bf16(oacc[ni], alo, bhi);
            }
        }
        __syncthreads();
    }

    float inv0 = 1.f / l0s;
    float inv1 = 1.f / l1s;
    #pragma unroll
    for (int ni = 0; ni < 8; ni++) {
        int col = wx * 64 + ni * 8 + 2 * lm;
        *(float2*)&ao[qbase + (size_t)row0 * Dc + col] =
            make_float2(oacc[ni][0] * inv0, oacc[ni][1] * inv0);
        *(float2*)&ao[qbase + (size_t)row1 * Dc + col] =
            make_float2(oacc[ni][2] * inv1, oacc[ni][3] * inv1);
    }
}

__global__ __launch_bounds__(256) void gate_kernel(
    const float* __restrict__ hn, const float* __restrict__ Wg,
    float* __restrict__ wslot, int* __restrict__ elist, int* __restrict__ ecount)
{
    int gtid = blockIdx.x * 256 + threadIdx.x;
    int t = gtid >> 5;
    int lane = gtid & 31;
    if (t >= NT) return;

    float acc[Ec];
    #pragma unroll
    for (int e = 0; e < Ec; e++) acc[e] = 0.f;
    const float* xr = hn + (size_t)t * Dc;
    for (int d = lane; d < Dc; d += 32) {
        float xv = xr[d];
        const float* wr = Wg + (size_t)d * Ec;
        #pragma unroll
        for (int e = 0; e < Ec; e++) acc[e] = fmaf(xv, wr[e], acc[e]);
    }
    #pragma unroll
    for (int e = 0; e < Ec; e++)
        #pragma unroll
        for (int m = 16; m >= 1; m >>= 1)
            acc[e] += __shfl_xor_sync(0xffffffffu, acc[e], m);

    if (lane == 0) {
        int e0 = 0; float l0 = acc[0];
        #pragma unroll
        for (int e = 1; e < Ec; e++) if (acc[e] > l0) { l0 = acc[e]; e0 = e; }
        int e1 = -1; float l1 = -3.4e38f;
        #pragma unroll
        for (int e = 0; e < Ec; e++) {
            if (e == e0) continue;
            if (acc[e] > l1) { l1 = acc[e]; e1 = e; }
        }
        float t1 = expf(l1 - l0);
        float w0 = 1.f / (1.f + t1);
        float w1 = t1 / (1.f + t1);
        wslot[2 * t]     = w0;
        wslot[2 * t + 1] = w1;
        int p0 = atomicAdd(&ecount[e0], 1);
        elist[e0 * NT + p0] = 2 * t;
        int p1 = atomicAdd(&ecount[e1], 1);
        elist[e1 * NT + p1] = 2 * t + 1;
    }
}

__global__ __launch_bounds__(256) void combine_kernel(
    const float* __restrict__ h, const float* __restrict__ moeout,
    float* __restrict__ out)
{
    size_t i = (size_t)blockIdx.x * 256 + threadIdx.x;
    size_t t = i >> 10, d = i & 1023;
    out[i] = h[i] + moeout[(2 * t) * (size_t)Dc + d]
                  + moeout[(2 * t + 1) * (size_t)Dc + d];
}

extern "C" void kernel_launch(void* const* d_in, const int* in_sizes, int n_in,
                              void* d_out, int out_size)
{
    const float* x     = (const float*)d_in[0];
    const float* freqs = (const float*)d_in[1];
    const float* g1    = (const float*)d_in[2];
    const float* b1    = (const float*)d_in[3];
    const float* g2    = (const float*)d_in[4];
    const float* b2    = (const float*)d_in[5];
    const float* Wq    = (const float*)d_in[6];
    const float* Wdkv  = (const float*)d_in[7];
    const float* Wuk   = (const float*)d_in[8];
    const float* Wuv   = (const float*)d_in[9];
    const float* Wo    = (const float*)d_in[10];
    const float* Wg    = (const float*)d_in[11];
    const float* W1    = (const float*)d_in[12];
    const float* W2    = (const float*)d_in[13];
    float* out = (float*)d_out;

    void* bufp = nullptr;
    cudaGetSymbolAddress(&bufp, g_buf);
    float* buf   = (float*)bufp;
    float* xn    = buf + OFF_XN;
    float* qb_   = buf + OFF_Q;
    float* kb_   = buf + OFF_K;
    float* vb_   = buf + OFF_V;
    float* lat   = buf + OFF_LAT;
    float* ao    = buf + OFF_AO;
    float* h     = buf + OFF_H;
    float* hn    = buf + OFF_HN;
    float* act   = buf + OFF_ACT;
    float* moeo  = buf + OFF_MOE;
    float* wslot = buf + OFF_WSLOT;
    int*   elist = (int*)(buf + OFF_ELIST);
    int*   ecnt  = (int*)(buf + OFF_ECNT);

    cudaFuncSetAttribute(flash_tc_kernel,
                         cudaFuncAttributeMaxDynamicSharedMemorySize, FLASH_SMEM);

    reset_kernel<<<1, 32>>>(ecnt);
    ln_kernel<<<NT, 256>>>(x, g1, b1, xn);

    tgemm_kernel<0, false><<<dim3(Dc / 128, NT / 128), 256>>>(
        xn, Wq, nullptr, qb_, NT, Dc, Dc, nullptr, nullptr, nullptr, 0, 0,
        nullptr, nullptr);
    tgemm_kernel<0, false><<<dim3(Lc / 128, NT / 128), 256>>>(
        xn, Wdkv, nullptr, lat, NT, Dc, Lc, nullptr, nullptr, nullptr, 0, 0,
        nullptr, nullptr);
    // fused Wuk (z=0) + Wuv (z=1)
    tgemm_kernel<0, false><<<dim3(Dc / 128, NT / 128, 2), 256>>>(
        lat, Wuk, nullptr, kb_, NT, Lc, Dc, nullptr, nullptr, nullptr, 0, 0,
        Wuv, vb_);

    rope_kernel<<<(NT * (Dc / 2)) / 256, 256>>>(qb_, kb_, freqs);

    flash_tc_kernel<<<dim3(Sc / 64, Hc, Bc), 256, FLASH_SMEM>>>(qb_, kb_, vb_, ao);

    tgemm_kernel<1, false><<<dim3(Dc / 128, NT / 128), 256>>>(
        ao, Wo, x, h, NT, Dc, Dc, nullptr, nullptr, nullptr, 0, 0,
        nullptr, nullptr);

    ln_kernel<<<NT, 256>>>(h, g2, b2, hn);

    gate_kernel<<<(NT * 32) / 256, 256>>>(hn, Wg, wslot, elist, ecnt);

    tgemm_kernel<2, true><<<dim3(Fc / 128, NT / 128, Ec), 256>>>(
        hn, W1, nullptr, act, 0, Dc, Fc, elist, ecnt, nullptr, 1, (size_t)Dc * Fc,
        nullptr, nullptr);
    tgemm_kernel<3, true><<<dim3(Dc / 128, NT / 128, Ec), 256>>>(
        act, W2, nullptr, moeo, 0, Fc, Dc, elist, ecnt, wslot, 0, (size_t)Fc * Dc,
        nullptr, nullptr);

    combine_kernel<<<(NT * Dc) / 256, 256>>>(h, moeo, out);
}